// round 11
// baseline (speedup 1.0000x reference)
#include <cuda_runtime.h>
#include <cuda_bf16.h>

constexpr int kB = 4, kS = 2048, kD = 1024, kH = 16, kDK = 64;
constexpr int kKS = 3072;  // split K dimension [hi | lo | hi]
constexpr int kCap = 32;   // shortlist capacity per row

__device__ __forceinline__ unsigned smem_u32(const void* p) {
  unsigned a;
  asm("{ .reg .u64 t; cvta.to.shared.u64 t, %1; cvt.u32.u64 %0, t; }"
      : "=r"(a) : "l"(p));
  return a;
}

// ---------------- mma.sync helpers (sm_80-class PTX) ----------------
__device__ __forceinline__ void cpasync16(unsigned dst, const void* src) {
  asm volatile("cp.async.ca.shared.global [%0], [%1], 16;" :: "r"(dst), "l"(src));
}
__device__ __forceinline__ void ldmx4(unsigned* r, unsigned addr) {
  asm volatile("ldmatrix.sync.aligned.m8n8.x4.shared.b16 {%0,%1,%2,%3}, [%4];"
               : "=r"(r[0]), "=r"(r[1]), "=r"(r[2]), "=r"(r[3]) : "r"(addr));
}
__device__ __forceinline__ void ldmx2(unsigned* r, unsigned addr) {
  asm volatile("ldmatrix.sync.aligned.m8n8.x2.shared.b16 {%0,%1}, [%2];"
               : "=r"(r[0]), "=r"(r[1]) : "r"(addr));
}
__device__ __forceinline__ void mma_bf16(float* d, const unsigned* a,
                                         unsigned b0, unsigned b1) {
  asm volatile(
      "mma.sync.aligned.m16n8k16.row.col.f32.bf16.bf16.f32 "
      "{%0,%1,%2,%3}, {%4,%5,%6,%7}, {%8,%9}, {%0,%1,%2,%3};"
      : "+f"(d[0]), "+f"(d[1]), "+f"(d[2]), "+f"(d[3])
      : "r"(a[0]), "r"(a[1]), "r"(a[2]), "r"(a[3]), "r"(b0), "r"(b1));
}

// ---------------- scratch ----------------
__device__ __align__(16) float g_q [(size_t)kB * kH * kS * kDK];
__device__ __align__(16) float g_k [(size_t)kB * kH * kS * kDK];
__device__ __align__(16) float g_v [(size_t)kB * kH * kS * kDK];
__device__ __align__(16) __nv_bfloat16 g_xs [(size_t)kB * kS * kKS];
__device__ __align__(16) __nv_bfloat16 g_ws [(size_t)3 * kH * kDK * kKS];
__device__ __align__(16) __nv_bfloat16 g_wos[(size_t)kD * kKS];
__device__ __align__(16) __nv_bfloat16 g_aos[(size_t)kB * kS * kKS];
__device__ int            g_cnt [(size_t)kB * kH * kS];
__device__ unsigned short g_slot[(size_t)kB * kH * kS * kCap];

__device__ __forceinline__ void split1(float x, unsigned short& h,
                                       unsigned short& l) {
  __nv_bfloat16 hb = __float2bfloat16_rn(x);
  __nv_bfloat16 lb = __float2bfloat16_rn(x - __bfloat162float(hb));
  h = __bfloat16_as_ushort(hb);
  l = __bfloat16_as_ushort(lb);
}

__device__ __forceinline__ uint4 pack8hi(const float* v) {
  unsigned short h[8];
#pragma unroll
  for (int j = 0; j < 8; ++j)
    h[j] = __bfloat16_as_ushort(__float2bfloat16_rn(v[j]));
  return make_uint4((unsigned)h[0] | ((unsigned)h[1] << 16),
                    (unsigned)h[2] | ((unsigned)h[3] << 16),
                    (unsigned)h[4] | ((unsigned)h[5] << 16),
                    (unsigned)h[6] | ((unsigned)h[7] << 16));
}

// ---------------- split kernels ----------------
__global__ __launch_bounds__(256) void split_act_kernel(
    const float* __restrict__ src, __nv_bfloat16* __restrict__ dst) {
  const int m = blockIdx.x;
  const int t = threadIdx.x;
  float4 v = *(const float4*)&src[(size_t)m * kD + t * 4];
  unsigned short h[4], l[4];
  split1(v.x, h[0], l[0]); split1(v.y, h[1], l[1]);
  split1(v.z, h[2], l[2]); split1(v.w, h[3], l[3]);
  uint2 hp = make_uint2((unsigned)h[0] | ((unsigned)h[1] << 16),
                        (unsigned)h[2] | ((unsigned)h[3] << 16));
  uint2 lp = make_uint2((unsigned)l[0] | ((unsigned)l[1] << 16),
                        (unsigned)l[2] | ((unsigned)l[3] << 16));
  __nv_bfloat16* base = dst + (size_t)m * kKS;
  *(uint2*)(base + t * 4) = hp;
  *(uint2*)(base + 1024 + t * 4) = lp;
  *(uint2*)(base + 2048 + t * 4) = hp;
}

__global__ __launch_bounds__(256) void split_w_kernel(
    const float* __restrict__ Wq, const float* __restrict__ Wk,
    const float* __restrict__ Wv) {
  const int ng = blockIdx.x;
  const int mat = ng >> 10;
  const int h = (ng >> 6) & 15;
  const int n = ng & 63;
  const float* W = (mat == 0 ? Wq : (mat == 1 ? Wk : Wv));
  const float* src = W + (size_t)h * kD * kDK + n;
  __nv_bfloat16* dst = g_ws + (size_t)ng * kKS;
#pragma unroll
  for (int it = 0; it < 4; ++it) {
    int d = threadIdx.x + it * 256;
    unsigned short hh, ll;
    split1(src[(size_t)d * kDK], hh, ll);
    dst[d] = __ushort_as_bfloat16(hh);
    dst[1024 + d] = __ushort_as_bfloat16(hh);
    dst[2048 + d] = __ushort_as_bfloat16(ll);
  }
}

__global__ __launch_bounds__(256) void split_wo_kernel(
    const float* __restrict__ Wo) {
  const int n = blockIdx.x;
  __nv_bfloat16* dst = g_wos + (size_t)n * kKS;
#pragma unroll
  for (int it = 0; it < 4; ++it) {
    int d = threadIdx.x + it * 256;
    unsigned short hh, ll;
    split1(Wo[(size_t)d * kD + n], hh, ll);
    dst[d] = __ushort_as_bfloat16(hh);
    dst[1024 + d] = __ushort_as_bfloat16(hh);
    dst[2048 + d] = __ushort_as_bfloat16(ll);
  }
}

// ---------------------------------------------------------------------------
// HMMA GEMM: C[128 x 128] = A[128 x 3072] * B[128 x 3072]^T (bf16 -> f32).
// 256 thr = 8 warps (2M x 4N), warp tile 64x32.
// 3-stage cp.async pipeline, ONE __syncthreads per chunk.
// smem: 3 x (A 16KB + B 16KB) = 98304 B; 2 blocks/SM.
// ---------------------------------------------------------------------------
__global__ __launch_bounds__(256) void mm_bf16_kernel(
    const __nv_bfloat16* __restrict__ A, const __nv_bfloat16* __restrict__ Bm,
    float* __restrict__ outP, int mode) {
  extern __shared__ char smem[];
  const unsigned sbase = smem_u32(smem);
  const unsigned aA[3] = {sbase, sbase + 32768, sbase + 65536};
  const unsigned aB[3] = {sbase + 16384, sbase + 49152, sbase + 81920};

  const int tid = threadIdx.x;
  const int wid = tid >> 5, lane = tid & 31;
  const int m0 = blockIdx.x * 128, n0 = blockIdx.y * 128;
  const int wm = (wid >> 2) * 64, wn = (wid & 3) * 32;
  const __nv_bfloat16* Asrc = A + (size_t)m0 * kKS;
  const __nv_bfloat16* Bsrc = Bm + (size_t)n0 * kKS;

  float acc[4][4][4];
#pragma unroll
  for (int mi = 0; mi < 4; ++mi)
#pragma unroll
    for (int ni = 0; ni < 4; ++ni)
#pragma unroll
      for (int r = 0; r < 4; ++r) acc[mi][ni][r] = 0.f;

#define STAGE(sbuf, ch)                                                        \
  do {                                                                         \
    _Pragma("unroll") for (int i_ = 0; i_ < 4; ++i_) {                         \
      int idx_ = tid + i_ * 256;                                               \
      int r_ = idx_ >> 3, sg_ = idx_ & 7;                                      \
      unsigned sw_ = ((unsigned)(sg_ ^ (r_ & 7))) << 4;                        \
      cpasync16(aA[sbuf] + r_ * 128 + sw_,                                     \
                Asrc + (size_t)r_ * kKS + (ch) * 64 + sg_ * 8);                \
      cpasync16(aB[sbuf] + r_ * 128 + sw_,                                     \
                Bsrc + (size_t)r_ * kKS + (ch) * 64 + sg_ * 8);                \
    }                                                                          \
    asm volatile("cp.async.commit_group;" ::: "memory");                       \
  } while (0)

  constexpr int NC = kKS / 64;  // 48
  STAGE(0, 0);
  STAGE(1, 1);
  for (int ch = 0; ch < NC; ++ch) {
    const int s = ch % 3;
    // own groups: ensure chunk ch landed (<=1 pending afterwards)
    if (ch < NC - 1) {
      asm volatile("cp.async.wait_group 1;" ::: "memory");
    } else {
      asm volatile("cp.async.wait_group 0;" ::: "memory");
    }
    __syncthreads();  // all threads waited for ch AND finished mma(ch-1)
    if (ch + 2 < NC) STAGE((ch + 2) % 3, ch + 2);
#pragma unroll
    for (int ks = 0; ks < 4; ++ks) {
      unsigned af[4][4], bf[4][2];
#pragma unroll
      for (int mi = 0; mi < 4; ++mi) {
        int row = wm + mi * 16 + (lane & 15);
        int cs = ks * 2 + (lane >> 4);
        ldmx4(af[mi], aA[s] + row * 128 + ((unsigned)(cs ^ (row & 7)) << 4));
      }
#pragma unroll
      for (int ni = 0; ni < 4; ++ni) {
        int row = wn + ni * 8 + (lane & 7);
        int cs = ks * 2 + ((lane >> 3) & 1);
        ldmx2(bf[ni], aB[s] + row * 128 + ((unsigned)(cs ^ (row & 7)) << 4));
      }
#pragma unroll
      for (int mi = 0; mi < 4; ++mi)
#pragma unroll
        for (int ni = 0; ni < 4; ++ni)
          mma_bf16(acc[mi][ni], af[mi], bf[ni][0], bf[ni][1]);
    }
  }
#undef STAGE

  const int b = m0 >> 11;
  const int mat = n0 >> 10;
  float* qkvout = (mat == 0 ? g_q : (mat == 1 ? g_k : g_v));
#pragma unroll
  for (int mi = 0; mi < 4; ++mi) {
#pragma unroll
    for (int ni = 0; ni < 4; ++ni) {
      int rl = wm + mi * 16 + (lane >> 2);
      int n = n0 + wn + ni * 8 + (lane & 3) * 2;
      if (mode == 0) {
        int h = (n >> 6) & 15, dk = n & 63;
        size_t rowbase = (size_t)(b * kH + h) * kS + (m0 & (kS - 1));
        *(float2*)&qkvout[(rowbase + rl) * kDK + dk] =
            make_float2(acc[mi][ni][0], acc[mi][ni][1]);
        *(float2*)&qkvout[(rowbase + rl + 8) * kDK + dk] =
            make_float2(acc[mi][ni][2], acc[mi][ni][3]);
      } else {
        int m = m0 + rl;
        *(float2*)&outP[(size_t)m * kD + n] =
            make_float2(acc[mi][ni][0], acc[mi][ni][1]);
        *(float2*)&outP[(size_t)(m + 8) * kD + n] =
            make_float2(acc[mi][ni][2], acc[mi][ni][3]);
      }
    }
  }
}

// ---------------------------------------------------------------------------
// attn_smax: S ~= Qhi Khi^T via HMMA (single product), row max + shortlist.
// Margin 70 covers dropped-cross-term noise (sigma ~2.3) with slack.
// smem: Qhi 16K + Khi 16K + cnt 512 + slots 8K = 41472 B.
// ---------------------------------------------------------------------------
__global__ __launch_bounds__(256) void attn_smax_kernel() {
  extern __shared__ char sm[];
  const unsigned sb = smem_u32(sm);
  const unsigned aQhi = sb, aKhi = sb + 16384;
  int* scnt = (int*)(sm + 32768);
  unsigned short* stid = (unsigned short*)(sm + 33280);

  const int tid = threadIdx.x;
  const int warp = tid >> 5, lane = tid & 31;
  const int qt = blockIdx.x, h = blockIdx.y, b = blockIdx.z;
  const int bh = b * kH + h;

  if (tid < 128) scnt[tid] = 0;

  const float* qsrc = g_q + ((size_t)bh * kS + qt * 128) * kDK;
#pragma unroll
  for (int it = 0; it < 4; ++it) {
    int idx = tid + it * 256;
    int row = idx >> 3, g = idx & 7;
    float v[8];
    float4 v0 = *(const float4*)&qsrc[(size_t)row * kDK + g * 8];
    float4 v1 = *(const float4*)&qsrc[(size_t)row * kDK + g * 8 + 4];
    v[0] = v0.x * 0.125f; v[1] = v0.y * 0.125f; v[2] = v0.z * 0.125f;
    v[3] = v0.w * 0.125f; v[4] = v1.x * 0.125f; v[5] = v1.y * 0.125f;
    v[6] = v1.z * 0.125f; v[7] = v1.w * 0.125f;
    unsigned sw = ((unsigned)(g ^ (row & 7))) << 4;
    *(uint4*)(sm + row * 128 + sw) = pack8hi(v);
  }

  float m0 = -3.0e38f, m1 = -3.0e38f;
  const int r0 = (warp << 4) + (lane >> 2);

  for (int kt = 0; kt < kS / 128; ++kt) {
    const float* ksrc = g_k + ((size_t)bh * kS + kt * 128) * kDK;
#pragma unroll
    for (int it = 0; it < 4; ++it) {
      int idx = tid + it * 256;
      int row = idx >> 3, g = idx & 7;
      float v[8];
      float4 v0 = *(const float4*)&ksrc[(size_t)row * kDK + g * 8];
      float4 v1 = *(const float4*)&ksrc[(size_t)row * kDK + g * 8 + 4];
      v[0] = v0.x; v[1] = v0.y; v[2] = v0.z; v[3] = v0.w;
      v[4] = v1.x; v[5] = v1.y; v[6] = v1.z; v[7] = v1.w;
      unsigned sw = ((unsigned)(g ^ (row & 7))) << 4;
      *(uint4*)(sm + 16384 + row * 128 + sw) = pack8hi(v);
    }
    __syncthreads();

    float acc[16][4];
#pragma unroll
    for (int tt = 0; tt < 16; ++tt)
#pragma unroll
      for (int j = 0; j < 4; ++j) acc[tt][j] = 0.f;

#pragma unroll
    for (int kc = 0; kc < 4; ++kc) {
      unsigned aHi[4];
      const int cs = kc * 2 + (lane >> 4);
      int rowq = (warp << 4) + (lane & 15);
      unsigned swq = ((unsigned)(cs ^ (rowq & 7))) << 4;
      ldmx4(aHi, aQhi + rowq * 128 + swq);
#pragma unroll
      for (int t3 = 0; t3 < 8; ++t3) {
        int rowb = t3 * 16 + (lane & 15);
        unsigned swb = ((unsigned)(cs ^ (rowb & 7))) << 4;
        unsigned kb[4];
        ldmx4(kb, aKhi + rowb * 128 + swb);
        mma_bf16(acc[t3 * 2], aHi, kb[0], kb[2]);
        mma_bf16(acc[t3 * 2 + 1], aHi, kb[1], kb[3]);
      }
    }

    float lm0 = -3.0e38f, lm1 = -3.0e38f;
#pragma unroll
    for (int tt = 0; tt < 16; ++tt) {
      lm0 = fmaxf(lm0, fmaxf(acc[tt][0], acc[tt][1]));
      lm1 = fmaxf(lm1, fmaxf(acc[tt][2], acc[tt][3]));
    }
    lm0 = fmaxf(lm0, __shfl_xor_sync(0xffffffffu, lm0, 1));
    lm0 = fmaxf(lm0, __shfl_xor_sync(0xffffffffu, lm0, 2));
    lm1 = fmaxf(lm1, __shfl_xor_sync(0xffffffffu, lm1, 1));
    lm1 = fmaxf(lm1, __shfl_xor_sync(0xffffffffu, lm1, 2));
    m0 = fmaxf(m0, lm0);
    m1 = fmaxf(m1, lm1);

    float th0 = m0 - 70.f, th1 = m1 - 70.f;
#pragma unroll
    for (int tt = 0; tt < 16; ++tt) {
      int tb = kt * 128 + tt * 8 + (lane & 3) * 2;
      if (acc[tt][0] > th0) {
        int i = atomicAdd(&scnt[r0], 1);
        if (i < kCap) stid[r0 * kCap + i] = (unsigned short)tb;
      }
      if (acc[tt][1] > th0) {
        int i = atomicAdd(&scnt[r0], 1);
        if (i < kCap) stid[r0 * kCap + i] = (unsigned short)(tb + 1);
      }
      if (acc[tt][2] > th1) {
        int i = atomicAdd(&scnt[r0 + 8], 1);
        if (i < kCap) stid[(r0 + 8) * kCap + i] = (unsigned short)tb;
      }
      if (acc[tt][3] > th1) {
        int i = atomicAdd(&scnt[r0 + 8], 1);
        if (i < kCap) stid[(r0 + 8) * kCap + i] = (unsigned short)(tb + 1);
      }
    }
    __syncthreads();
  }

  if (tid < 128) {
    size_t row_g = ((size_t)bh * 16 + qt) * 128 + tid;
    int c = scnt[tid];
    g_cnt[row_g] = c;
    int cc = c < kCap ? c : kCap;
    for (int i = 0; i < cc; ++i) g_slot[row_g * kCap + i] = stid[tid * kCap + i];
  }
}

// ---------------------------------------------------------------------------
// attn_gather: warp per q-row; exact fp32 softmax over shortlist; gather V;
// writes the bf16 [hi|lo|hi] split panels of attn-out directly (no fp32
// round trip through global).
// ---------------------------------------------------------------------------
__global__ __launch_bounds__(256) void attn_gather_kernel() {
  const int warp = threadIdx.x >> 5, lane = threadIdx.x & 31;
  const size_t row_g = (size_t)blockIdx.x * 8 + warp;
  const int qrow = (int)(row_g & 127);
  const int qt = (int)((row_g >> 7) & 15);
  const int h = (int)((row_g >> 11) & 15);
  const int b = (int)(row_g >> 15);
  const int bh = b * kH + h;
  const int sq = qt * 128 + qrow;

  const float* qp = g_q + ((size_t)bh * kS + sq) * kDK;
  const float* kb = g_k + (size_t)bh * kS * kDK;
  const float* vb = g_v + (size_t)bh * kS * kDK;

  const float q0 = qp[lane] * 0.125f, q1 = qp[lane + 32] * 0.125f;
  const int cnt = g_cnt[row_g];

  float m = -3.0e38f, l = 0.f, a0 = 0.f, a1 = 0.f;
  if (cnt <= kCap) {
    const unsigned short* sl = g_slot + row_g * kCap;
    for (int i = 0; i < cnt; ++i) {
      int t = sl[i];
      float d = q0 * kb[(size_t)t * kDK + lane] + q1 * kb[(size_t)t * kDK + lane + 32];
#pragma unroll
      for (int o = 16; o > 0; o >>= 1) d += __shfl_xor_sync(0xffffffffu, d, o);
      m = fmaxf(m, d);
    }
    for (int i = 0; i < cnt; ++i) {
      int t = sl[i];
      float d = q0 * kb[(size_t)t * kDK + lane] + q1 * kb[(size_t)t * kDK + lane + 32];
#pragma unroll
      for (int o = 16; o > 0; o >>= 1) d += __shfl_xor_sync(0xffffffffu, d, o);
      float p = __expf(d - m);
      l += p;
      a0 += p * vb[(size_t)t * kDK + lane];
      a1 += p * vb[(size_t)t * kDK + lane + 32];
    }
  } else {
    for (int t = 0; t < kS; ++t) {
      float d = q0 * kb[(size_t)t * kDK + lane] + q1 * kb[(size_t)t * kDK + lane + 32];
#pragma unroll
      for (int o = 16; o > 0; o >>= 1) d += __shfl_xor_sync(0xffffffffu, d, o);
      float v0 = vb[(size_t)t * kDK + lane], v1 = vb[(size_t)t * kDK + lane + 32];
      if (d > m) {
        float c = __expf(m - d);
        m = d;
        l = l * c + 1.f;
        a0 = a0 * c + v0;
        a1 = a1 * c + v1;
      } else {
        float p = __expf(d - m);
        l += p;
        a0 += p * v0;
        a1 += p * v1;
      }
    }
  }
  float inv = 1.f / l;
  float o0 = a0 * inv, o1 = a1 * inv;
  unsigned short h0, l0, h1, l1;
  split1(o0, h0, l0);
  split1(o1, h1, l1);
  __nv_bfloat16* base = g_aos + ((size_t)b * kS + sq) * kKS + h * kDK;
  base[lane] = __ushort_as_bfloat16(h0);
  base[lane + 32] = __ushort_as_bfloat16(h1);
  base[1024 + lane] = __ushort_as_bfloat16(l0);
  base[1024 + lane + 32] = __ushort_as_bfloat16(l1);
  base[2048 + lane] = __ushort_as_bfloat16(h0);
  base[2048 + lane + 32] = __ushort_as_bfloat16(h1);
}

// ---------------------------------------------------------------------------
extern "C" void kernel_launch(void* const* d_in, const int* in_sizes, int n_in,
                              void* d_out, int out_size) {
  (void)in_sizes; (void)n_in; (void)out_size;
  const float* x  = (const float*)d_in[0];
  const float* Wq = (const float*)d_in[1];
  const float* Wk = (const float*)d_in[2];
  const float* Wv = (const float*)d_in[3];
  const float* Wo = (const float*)d_in[4];
  float* out = (float*)d_out;

  static int attr_set = 0;
  if (!attr_set) {
    cudaFuncSetAttribute(mm_bf16_kernel,
                         cudaFuncAttributeMaxDynamicSharedMemorySize, 98304);
    cudaFuncSetAttribute(attn_smax_kernel,
                         cudaFuncAttributeMaxDynamicSharedMemorySize, 41472);
    attr_set = 1;
  }

  __nv_bfloat16* xs;  cudaGetSymbolAddress((void**)&xs, g_xs);
  __nv_bfloat16* ws;  cudaGetSymbolAddress((void**)&ws, g_ws);
  __nv_bfloat16* wos; cudaGetSymbolAddress((void**)&wos, g_wos);
  __nv_bfloat16* aos; cudaGetSymbolAddress((void**)&aos, g_aos);

  split_act_kernel<<<kB * kS, 256>>>(x, xs);
  split_w_kernel<<<3 * kH * kDK, 256>>>(Wq, Wk, Wv);
  split_wo_kernel<<<kD, 256>>>(Wo);
  mm_bf16_kernel<<<dim3(kB * kS / 128, kKS / 128), 256, 98304>>>(xs, ws, nullptr, 0);
  attn_smax_kernel<<<dim3(kS / 128, kH, kB), 256, 41472>>>();
  attn_gather_kernel<<<kB * kH * kS / 8, 256>>>();
  mm_bf16_kernel<<<dim3(kB * kS / 128, kD / 128), 256, 98304>>>(aos, wos, out, 1);
}

// round 12
// speedup vs baseline: 1.0885x; 1.0885x over previous
#include <cuda_runtime.h>
#include <cuda_bf16.h>

constexpr int kB = 4, kS = 2048, kD = 1024, kH = 16, kDK = 64;
constexpr int kKS = 3072;  // split K dimension [hi | lo | hi]
constexpr int kCap = 32;   // shortlist capacity per row

__device__ __forceinline__ unsigned smem_u32(const void* p) {
  unsigned a;
  asm("{ .reg .u64 t; cvta.to.shared.u64 t, %1; cvt.u32.u64 %0, t; }"
      : "=r"(a) : "l"(p));
  return a;
}

// ---------------- mma.sync helpers (sm_80-class PTX) ----------------
__device__ __forceinline__ void cpasync16(unsigned dst, const void* src) {
  asm volatile("cp.async.ca.shared.global [%0], [%1], 16;" :: "r"(dst), "l"(src));
}
__device__ __forceinline__ void ldmx4(unsigned* r, unsigned addr) {
  asm volatile("ldmatrix.sync.aligned.m8n8.x4.shared.b16 {%0,%1,%2,%3}, [%4];"
               : "=r"(r[0]), "=r"(r[1]), "=r"(r[2]), "=r"(r[3]) : "r"(addr));
}
__device__ __forceinline__ void ldmx2(unsigned* r, unsigned addr) {
  asm volatile("ldmatrix.sync.aligned.m8n8.x2.shared.b16 {%0,%1}, [%2];"
               : "=r"(r[0]), "=r"(r[1]) : "r"(addr));
}
__device__ __forceinline__ void mma_bf16(float* d, const unsigned* a,
                                         unsigned b0, unsigned b1) {
  asm volatile(
      "mma.sync.aligned.m16n8k16.row.col.f32.bf16.bf16.f32 "
      "{%0,%1,%2,%3}, {%4,%5,%6,%7}, {%8,%9}, {%0,%1,%2,%3};"
      : "+f"(d[0]), "+f"(d[1]), "+f"(d[2]), "+f"(d[3])
      : "r"(a[0]), "r"(a[1]), "r"(a[2]), "r"(a[3]), "r"(b0), "r"(b1));
}

// ---------------- scratch ----------------
__device__ __align__(16) float g_q [(size_t)kB * kH * kS * kDK];
__device__ __align__(16) float g_k [(size_t)kB * kH * kS * kDK];
__device__ __align__(16) float g_v [(size_t)kB * kH * kS * kDK];
__device__ __align__(16) __nv_bfloat16 g_xs [(size_t)kB * kS * kKS];
__device__ __align__(16) __nv_bfloat16 g_ws [(size_t)3 * kH * kDK * kKS];
__device__ __align__(16) __nv_bfloat16 g_wos[(size_t)kD * kKS];
__device__ __align__(16) __nv_bfloat16 g_aos[(size_t)kB * kS * kKS];
__device__ int            g_cnt [(size_t)kB * kH * kS];
__device__ unsigned short g_slot[(size_t)kB * kH * kS * kCap];

__device__ __forceinline__ void split1(float x, unsigned short& h,
                                       unsigned short& l) {
  __nv_bfloat16 hb = __float2bfloat16_rn(x);
  __nv_bfloat16 lb = __float2bfloat16_rn(x - __bfloat162float(hb));
  h = __bfloat16_as_ushort(hb);
  l = __bfloat16_as_ushort(lb);
}

__device__ __forceinline__ uint4 pack8hi(const float* v) {
  unsigned short h[8];
#pragma unroll
  for (int j = 0; j < 8; ++j)
    h[j] = __bfloat16_as_ushort(__float2bfloat16_rn(v[j]));
  return make_uint4((unsigned)h[0] | ((unsigned)h[1] << 16),
                    (unsigned)h[2] | ((unsigned)h[3] << 16),
                    (unsigned)h[4] | ((unsigned)h[5] << 16),
                    (unsigned)h[6] | ((unsigned)h[7] << 16));
}

// ---------------- split kernels ----------------
__global__ __launch_bounds__(256) void split_act_kernel(
    const float* __restrict__ src, __nv_bfloat16* __restrict__ dst) {
  const int m = blockIdx.x;
  const int t = threadIdx.x;
  float4 v = *(const float4*)&src[(size_t)m * kD + t * 4];
  unsigned short h[4], l[4];
  split1(v.x, h[0], l[0]); split1(v.y, h[1], l[1]);
  split1(v.z, h[2], l[2]); split1(v.w, h[3], l[3]);
  uint2 hp = make_uint2((unsigned)h[0] | ((unsigned)h[1] << 16),
                        (unsigned)h[2] | ((unsigned)h[3] << 16));
  uint2 lp = make_uint2((unsigned)l[0] | ((unsigned)l[1] << 16),
                        (unsigned)l[2] | ((unsigned)l[3] << 16));
  __nv_bfloat16* base = dst + (size_t)m * kKS;
  *(uint2*)(base + t * 4) = hp;
  *(uint2*)(base + 1024 + t * 4) = lp;
  *(uint2*)(base + 2048 + t * 4) = hp;
}

__global__ __launch_bounds__(256) void split_w_kernel(
    const float* __restrict__ Wq, const float* __restrict__ Wk,
    const float* __restrict__ Wv) {
  const int ng = blockIdx.x;
  const int mat = ng >> 10;
  const int h = (ng >> 6) & 15;
  const int n = ng & 63;
  const float* W = (mat == 0 ? Wq : (mat == 1 ? Wk : Wv));
  const float* src = W + (size_t)h * kD * kDK + n;
  __nv_bfloat16* dst = g_ws + (size_t)ng * kKS;
#pragma unroll
  for (int it = 0; it < 4; ++it) {
    int d = threadIdx.x + it * 256;
    unsigned short hh, ll;
    split1(src[(size_t)d * kDK], hh, ll);
    dst[d] = __ushort_as_bfloat16(hh);
    dst[1024 + d] = __ushort_as_bfloat16(hh);
    dst[2048 + d] = __ushort_as_bfloat16(ll);
  }
}

__global__ __launch_bounds__(256) void split_wo_kernel(
    const float* __restrict__ Wo) {
  const int n = blockIdx.x;
  __nv_bfloat16* dst = g_wos + (size_t)n * kKS;
#pragma unroll
  for (int it = 0; it < 4; ++it) {
    int d = threadIdx.x + it * 256;
    unsigned short hh, ll;
    split1(Wo[(size_t)d * kD + n], hh, ll);
    dst[d] = __ushort_as_bfloat16(hh);
    dst[1024 + d] = __ushort_as_bfloat16(hh);
    dst[2048 + d] = __ushort_as_bfloat16(ll);
  }
}

// ---------------------------------------------------------------------------
// HMMA GEMM (exact R8/R10 configuration — measured 418 us, tensor 61%).
// C[128 x 128] = A[128 x 3072] * B[128 x 3072]^T (bf16 -> f32).
// 256 thr = 8 warps (2M x 4N), warp tile 64x32, cp.async double buffer.
// ---------------------------------------------------------------------------
__global__ __launch_bounds__(256) void mm_bf16_kernel(
    const __nv_bfloat16* __restrict__ A, const __nv_bfloat16* __restrict__ Bm,
    float* __restrict__ outP, int mode) {
  extern __shared__ char smem[];
  const unsigned sbase = smem_u32(smem);
  const unsigned aA[2] = {sbase, sbase + 16384};
  const unsigned aB[2] = {sbase + 32768, sbase + 49152};

  const int tid = threadIdx.x;
  const int wid = tid >> 5, lane = tid & 31;
  const int m0 = blockIdx.x * 128, n0 = blockIdx.y * 128;
  const int wm = (wid >> 2) * 64, wn = (wid & 3) * 32;
  const __nv_bfloat16* Asrc = A + (size_t)m0 * kKS;
  const __nv_bfloat16* Bsrc = Bm + (size_t)n0 * kKS;

  float acc[4][4][4];
#pragma unroll
  for (int mi = 0; mi < 4; ++mi)
#pragma unroll
    for (int ni = 0; ni < 4; ++ni)
#pragma unroll
      for (int r = 0; r < 4; ++r) acc[mi][ni][r] = 0.f;

#define STAGE(sbuf, ch)                                                        \
  do {                                                                         \
    _Pragma("unroll") for (int i_ = 0; i_ < 4; ++i_) {                         \
      int idx_ = tid + i_ * 256;                                               \
      int r_ = idx_ >> 3, sg_ = idx_ & 7;                                      \
      unsigned sw_ = ((unsigned)(sg_ ^ (r_ & 7))) << 4;                        \
      cpasync16(aA[sbuf] + r_ * 128 + sw_,                                     \
                Asrc + (size_t)r_ * kKS + (ch) * 64 + sg_ * 8);                \
      cpasync16(aB[sbuf] + r_ * 128 + sw_,                                     \
                Bsrc + (size_t)r_ * kKS + (ch) * 64 + sg_ * 8);                \
    }                                                                          \
    asm volatile("cp.async.commit_group;" ::: "memory");                       \
  } while (0)

  STAGE(0, 0);
  for (int ch = 0; ch < kKS / 64; ++ch) {
    const int s = ch & 1;
    if (ch < kKS / 64 - 1) {
      STAGE(s ^ 1, ch + 1);
      asm volatile("cp.async.wait_group 1;" ::: "memory");
    } else {
      asm volatile("cp.async.wait_group 0;" ::: "memory");
    }
    __syncthreads();
#pragma unroll
    for (int ks = 0; ks < 4; ++ks) {
      unsigned af[4][4], bf[4][2];
#pragma unroll
      for (int mi = 0; mi < 4; ++mi) {
        int row = wm + mi * 16 + (lane & 15);
        int cs = ks * 2 + (lane >> 4);
        ldmx4(af[mi], aA[s] + row * 128 + ((unsigned)(cs ^ (row & 7)) << 4));
      }
#pragma unroll
      for (int ni = 0; ni < 4; ++ni) {
        int row = wn + ni * 8 + (lane & 7);
        int cs = ks * 2 + ((lane >> 3) & 1);
        ldmx2(bf[ni], aB[s] + row * 128 + ((unsigned)(cs ^ (row & 7)) << 4));
      }
#pragma unroll
      for (int mi = 0; mi < 4; ++mi)
#pragma unroll
        for (int ni = 0; ni < 4; ++ni)
          mma_bf16(acc[mi][ni], af[mi], bf[ni][0], bf[ni][1]);
    }
    __syncthreads();
  }
#undef STAGE

  const int b = m0 >> 11;
  const int mat = n0 >> 10;
  float* qkvout = (mat == 0 ? g_q : (mat == 1 ? g_k : g_v));
#pragma unroll
  for (int mi = 0; mi < 4; ++mi) {
#pragma unroll
    for (int ni = 0; ni < 4; ++ni) {
      int rl = wm + mi * 16 + (lane >> 2);
      int n = n0 + wn + ni * 8 + (lane & 3) * 2;
      if (mode == 0) {
        int h = (n >> 6) & 15, dk = n & 63;
        size_t rowbase = (size_t)(b * kH + h) * kS + (m0 & (kS - 1));
        *(float2*)&qkvout[(rowbase + rl) * kDK + dk] =
            make_float2(acc[mi][ni][0], acc[mi][ni][1]);
        *(float2*)&qkvout[(rowbase + rl + 8) * kDK + dk] =
            make_float2(acc[mi][ni][2], acc[mi][ni][3]);
      } else {
        int m = m0 + rl;
        *(float2*)&outP[(size_t)m * kD + n] =
            make_float2(acc[mi][ni][0], acc[mi][ni][1]);
        *(float2*)&outP[(size_t)(m + 8) * kD + n] =
            make_float2(acc[mi][ni][2], acc[mi][ni][3]);
      }
    }
  }
}

// ---------------------------------------------------------------------------
// attn_smax: S ~= Qhi Khi^T via HMMA (single product), row max + shortlist.
// Margin 70 covers dropped-cross-term noise (sigma ~2.3) with slack.
// smem: Qhi 16K + Khi 16K + cnt 512 + slots 8K = 41472 B.
// ---------------------------------------------------------------------------
__global__ __launch_bounds__(256) void attn_smax_kernel() {
  extern __shared__ char sm[];
  const unsigned sb = smem_u32(sm);
  const unsigned aQhi = sb, aKhi = sb + 16384;
  int* scnt = (int*)(sm + 32768);
  unsigned short* stid = (unsigned short*)(sm + 33280);

  const int tid = threadIdx.x;
  const int warp = tid >> 5, lane = tid & 31;
  const int qt = blockIdx.x, h = blockIdx.y, b = blockIdx.z;
  const int bh = b * kH + h;

  if (tid < 128) scnt[tid] = 0;

  const float* qsrc = g_q + ((size_t)bh * kS + qt * 128) * kDK;
#pragma unroll
  for (int it = 0; it < 4; ++it) {
    int idx = tid + it * 256;
    int row = idx >> 3, g = idx & 7;
    float v[8];
    float4 v0 = *(const float4*)&qsrc[(size_t)row * kDK + g * 8];
    float4 v1 = *(const float4*)&qsrc[(size_t)row * kDK + g * 8 + 4];
    v[0] = v0.x * 0.125f; v[1] = v0.y * 0.125f; v[2] = v0.z * 0.125f;
    v[3] = v0.w * 0.125f; v[4] = v1.x * 0.125f; v[5] = v1.y * 0.125f;
    v[6] = v1.z * 0.125f; v[7] = v1.w * 0.125f;
    unsigned sw = ((unsigned)(g ^ (row & 7))) << 4;
    *(uint4*)(sm + row * 128 + sw) = pack8hi(v);
  }

  float m0 = -3.0e38f, m1 = -3.0e38f;
  const int r0 = (warp << 4) + (lane >> 2);

  for (int kt = 0; kt < kS / 128; ++kt) {
    const float* ksrc = g_k + ((size_t)bh * kS + kt * 128) * kDK;
#pragma unroll
    for (int it = 0; it < 4; ++it) {
      int idx = tid + it * 256;
      int row = idx >> 3, g = idx & 7;
      float v[8];
      float4 v0 = *(const float4*)&ksrc[(size_t)row * kDK + g * 8];
      float4 v1 = *(const float4*)&ksrc[(size_t)row * kDK + g * 8 + 4];
      v[0] = v0.x; v[1] = v0.y; v[2] = v0.z; v[3] = v0.w;
      v[4] = v1.x; v[5] = v1.y; v[6] = v1.z; v[7] = v1.w;
      unsigned sw = ((unsigned)(g ^ (row & 7))) << 4;
      *(uint4*)(sm + 16384 + row * 128 + sw) = pack8hi(v);
    }
    __syncthreads();

    float acc[16][4];
#pragma unroll
    for (int tt = 0; tt < 16; ++tt)
#pragma unroll
      for (int j = 0; j < 4; ++j) acc[tt][j] = 0.f;

#pragma unroll
    for (int kc = 0; kc < 4; ++kc) {
      unsigned aHi[4];
      const int cs = kc * 2 + (lane >> 4);
      int rowq = (warp << 4) + (lane & 15);
      unsigned swq = ((unsigned)(cs ^ (rowq & 7))) << 4;
      ldmx4(aHi, aQhi + rowq * 128 + swq);
#pragma unroll
      for (int t3 = 0; t3 < 8; ++t3) {
        int rowb = t3 * 16 + (lane & 15);
        unsigned swb = ((unsigned)(cs ^ (rowb & 7))) << 4;
        unsigned kb[4];
        ldmx4(kb, aKhi + rowb * 128 + swb);
        mma_bf16(acc[t3 * 2], aHi, kb[0], kb[2]);
        mma_bf16(acc[t3 * 2 + 1], aHi, kb[1], kb[3]);
      }
    }

    float lm0 = -3.0e38f, lm1 = -3.0e38f;
#pragma unroll
    for (int tt = 0; tt < 16; ++tt) {
      lm0 = fmaxf(lm0, fmaxf(acc[tt][0], acc[tt][1]));
      lm1 = fmaxf(lm1, fmaxf(acc[tt][2], acc[tt][3]));
    }
    lm0 = fmaxf(lm0, __shfl_xor_sync(0xffffffffu, lm0, 1));
    lm0 = fmaxf(lm0, __shfl_xor_sync(0xffffffffu, lm0, 2));
    lm1 = fmaxf(lm1, __shfl_xor_sync(0xffffffffu, lm1, 1));
    lm1 = fmaxf(lm1, __shfl_xor_sync(0xffffffffu, lm1, 2));
    m0 = fmaxf(m0, lm0);
    m1 = fmaxf(m1, lm1);

    float th0 = m0 - 70.f, th1 = m1 - 70.f;
#pragma unroll
    for (int tt = 0; tt < 16; ++tt) {
      int tb = kt * 128 + tt * 8 + (lane & 3) * 2;
      if (acc[tt][0] > th0) {
        int i = atomicAdd(&scnt[r0], 1);
        if (i < kCap) stid[r0 * kCap + i] = (unsigned short)tb;
      }
      if (acc[tt][1] > th0) {
        int i = atomicAdd(&scnt[r0], 1);
        if (i < kCap) stid[r0 * kCap + i] = (unsigned short)(tb + 1);
      }
      if (acc[tt][2] > th1) {
        int i = atomicAdd(&scnt[r0 + 8], 1);
        if (i < kCap) stid[(r0 + 8) * kCap + i] = (unsigned short)tb;
      }
      if (acc[tt][3] > th1) {
        int i = atomicAdd(&scnt[r0 + 8], 1);
        if (i < kCap) stid[(r0 + 8) * kCap + i] = (unsigned short)(tb + 1);
      }
    }
    __syncthreads();
  }

  if (tid < 128) {
    size_t row_g = ((size_t)bh * 16 + qt) * 128 + tid;
    int c = scnt[tid];
    g_cnt[row_g] = c;
    int cc = c < kCap ? c : kCap;
    for (int i = 0; i < cc; ++i) g_slot[row_g * kCap + i] = stid[tid * kCap + i];
  }
}

// ---------------------------------------------------------------------------
// attn_gather: warp per q-row; exact fp32 softmax over shortlist; gather V;
// writes the bf16 [hi|lo|hi] split panels of attn-out directly.
// ---------------------------------------------------------------------------
__global__ __launch_bounds__(256) void attn_gather_kernel() {
  const int warp = threadIdx.x >> 5, lane = threadIdx.x & 31;
  const size_t row_g = (size_t)blockIdx.x * 8 + warp;
  const int qrow = (int)(row_g & 127);
  const int qt = (int)((row_g >> 7) & 15);
  const int h = (int)((row_g >> 11) & 15);
  const int b = (int)(row_g >> 15);
  const int bh = b * kH + h;
  const int sq = qt * 128 + qrow;

  const float* qp = g_q + ((size_t)bh * kS + sq) * kDK;
  const float* kb = g_k + (size_t)bh * kS * kDK;
  const float* vb = g_v + (size_t)bh * kS * kDK;

  const float q0 = qp[lane] * 0.125f, q1 = qp[lane + 32] * 0.125f;
  const int cnt = g_cnt[row_g];

  float m = -3.0e38f, l = 0.f, a0 = 0.f, a1 = 0.f;
  if (cnt <= kCap) {
    const unsigned short* sl = g_slot + row_g * kCap;
    for (int i = 0; i < cnt; ++i) {
      int t = sl[i];
      float d = q0 * kb[(size_t)t * kDK + lane] + q1 * kb[(size_t)t * kDK + lane + 32];
#pragma unroll
      for (int o = 16; o > 0; o >>= 1) d += __shfl_xor_sync(0xffffffffu, d, o);
      m = fmaxf(m, d);
    }
    for (int i = 0; i < cnt; ++i) {
      int t = sl[i];
      float d = q0 * kb[(size_t)t * kDK + lane] + q1 * kb[(size_t)t * kDK + lane + 32];
#pragma unroll
      for (int o = 16; o > 0; o >>= 1) d += __shfl_xor_sync(0xffffffffu, d, o);
      float p = __expf(d - m);
      l += p;
      a0 += p * vb[(size_t)t * kDK + lane];
      a1 += p * vb[(size_t)t * kDK + lane + 32];
    }
  } else {
    for (int t = 0; t < kS; ++t) {
      float d = q0 * kb[(size_t)t * kDK + lane] + q1 * kb[(size_t)t * kDK + lane + 32];
#pragma unroll
      for (int o = 16; o > 0; o >>= 1) d += __shfl_xor_sync(0xffffffffu, d, o);
      float v0 = vb[(size_t)t * kDK + lane], v1 = vb[(size_t)t * kDK + lane + 32];
      if (d > m) {
        float c = __expf(m - d);
        m = d;
        l = l * c + 1.f;
        a0 = a0 * c + v0;
        a1 = a1 * c + v1;
      } else {
        float p = __expf(d - m);
        l += p;
        a0 += p * v0;
        a1 += p * v1;
      }
    }
  }
  float inv = 1.f / l;
  float o0 = a0 * inv, o1 = a1 * inv;
  unsigned short h0, l0, h1, l1;
  split1(o0, h0, l0);
  split1(o1, h1, l1);
  __nv_bfloat16* base = g_aos + ((size_t)b * kS + sq) * kKS + h * kDK;
  base[lane] = __ushort_as_bfloat16(h0);
  base[lane + 32] = __ushort_as_bfloat16(h1);
  base[1024 + lane] = __ushort_as_bfloat16(l0);
  base[1024 + lane + 32] = __ushort_as_bfloat16(l1);
  base[2048 + lane] = __ushort_as_bfloat16(h0);
  base[2048 + lane + 32] = __ushort_as_bfloat16(h1);
}

// ---------------------------------------------------------------------------
extern "C" void kernel_launch(void* const* d_in, const int* in_sizes, int n_in,
                              void* d_out, int out_size) {
  (void)in_sizes; (void)n_in; (void)out_size;
  const float* x  = (const float*)d_in[0];
  const float* Wq = (const float*)d_in[1];
  const float* Wk = (const float*)d_in[2];
  const float* Wv = (const float*)d_in[3];
  const float* Wo = (const float*)d_in[4];
  float* out = (float*)d_out;

  static int attr_set = 0;
  if (!attr_set) {
    cudaFuncSetAttribute(mm_bf16_kernel,
                         cudaFuncAttributeMaxDynamicSharedMemorySize, 65536);
    cudaFuncSetAttribute(attn_smax_kernel,
                         cudaFuncAttributeMaxDynamicSharedMemorySize, 41472);
    attr_set = 1;
  }

  __nv_bfloat16* xs;  cudaGetSymbolAddress((void**)&xs, g_xs);
  __nv_bfloat16* ws;  cudaGetSymbolAddress((void**)&ws, g_ws);
  __nv_bfloat16* wos; cudaGetSymbolAddress((void**)&wos, g_wos);
  __nv_bfloat16* aos; cudaGetSymbolAddress((void**)&aos, g_aos);

  split_act_kernel<<<kB * kS, 256>>>(x, xs);
  split_w_kernel<<<3 * kH * kDK, 256>>>(Wq, Wk, Wv);
  split_wo_kernel<<<kD, 256>>>(Wo);
  mm_bf16_kernel<<<dim3(kB * kS / 128, kKS / 128), 256, 65536>>>(xs, ws, nullptr, 0);
  attn_smax_kernel<<<dim3(kS / 128, kH, kB), 256, 41472>>>();
  attn_gather_kernel<<<kB * kH * kS / 8, 256>>>();
  mm_bf16_kernel<<<dim3(kB * kS / 128, kD / 128), 256, 65536>>>(aos, wos, out, 1);
}

// round 13
// speedup vs baseline: 1.1004x; 1.0109x over previous
#include <cuda_runtime.h>
#include <cuda_bf16.h>

constexpr int kB = 4, kS = 2048, kD = 1024, kH = 16, kDK = 64;
constexpr int kKS = 3072;  // split K dimension [hi | lo | hi]
constexpr int kCap = 32;   // shortlist capacity per row

__device__ __forceinline__ unsigned smem_u32(const void* p) {
  unsigned a;
  asm("{ .reg .u64 t; cvta.to.shared.u64 t, %1; cvt.u32.u64 %0, t; }"
      : "=r"(a) : "l"(p));
  return a;
}

// ---------------- mma.sync helpers (sm_80-class PTX) ----------------
__device__ __forceinline__ void cpasync16(unsigned dst, const void* src) {
  asm volatile("cp.async.cg.shared.global [%0], [%1], 16;" :: "r"(dst), "l"(src));
}
__device__ __forceinline__ void ldmx4(unsigned* r, unsigned addr) {
  asm volatile("ldmatrix.sync.aligned.m8n8.x4.shared.b16 {%0,%1,%2,%3}, [%4];"
               : "=r"(r[0]), "=r"(r[1]), "=r"(r[2]), "=r"(r[3]) : "r"(addr));
}
__device__ __forceinline__ void mma_bf16(float* d, const unsigned* a,
                                         unsigned b0, unsigned b1) {
  asm volatile(
      "mma.sync.aligned.m16n8k16.row.col.f32.bf16.bf16.f32 "
      "{%0,%1,%2,%3}, {%4,%5,%6,%7}, {%8,%9}, {%0,%1,%2,%3};"
      : "+f"(d[0]), "+f"(d[1]), "+f"(d[2]), "+f"(d[3])
      : "r"(a[0]), "r"(a[1]), "r"(a[2]), "r"(a[3]), "r"(b0), "r"(b1));
}

// ---------------- scratch ----------------
__device__ __align__(16) float g_q [(size_t)kB * kH * kS * kDK];
__device__ __align__(16) float g_k [(size_t)kB * kH * kS * kDK];
__device__ __align__(16) float g_v [(size_t)kB * kH * kS * kDK];
__device__ __align__(16) __nv_bfloat16 g_xs [(size_t)kB * kS * kKS];
__device__ __align__(16) __nv_bfloat16 g_ws [(size_t)3 * kH * kDK * kKS];
__device__ __align__(16) __nv_bfloat16 g_wos[(size_t)kD * kKS];
__device__ __align__(16) __nv_bfloat16 g_aos[(size_t)kB * kS * kKS];
__device__ int            g_cnt [(size_t)kB * kH * kS];
__device__ float          g_rowmax[(size_t)kB * kH * kS];
__device__ unsigned short g_slot[(size_t)kB * kH * kS * kCap];

__device__ __forceinline__ void split1(float x, unsigned short& h,
                                       unsigned short& l) {
  __nv_bfloat16 hb = __float2bfloat16_rn(x);
  __nv_bfloat16 lb = __float2bfloat16_rn(x - __bfloat162float(hb));
  h = __bfloat16_as_ushort(hb);
  l = __bfloat16_as_ushort(lb);
}

__device__ __forceinline__ uint4 pack8hi(const float* v) {
  unsigned short h[8];
#pragma unroll
  for (int j = 0; j < 8; ++j)
    h[j] = __bfloat16_as_ushort(__float2bfloat16_rn(v[j]));
  return make_uint4((unsigned)h[0] | ((unsigned)h[1] << 16),
                    (unsigned)h[2] | ((unsigned)h[3] << 16),
                    (unsigned)h[4] | ((unsigned)h[5] << 16),
                    (unsigned)h[6] | ((unsigned)h[7] << 16));
}

// ---------------- split kernels ----------------
__global__ __launch_bounds__(256) void split_act_kernel(
    const float* __restrict__ src, __nv_bfloat16* __restrict__ dst) {
  const int m = blockIdx.x;
  const int t = threadIdx.x;
  float4 v = *(const float4*)&src[(size_t)m * kD + t * 4];
  unsigned short h[4], l[4];
  split1(v.x, h[0], l[0]); split1(v.y, h[1], l[1]);
  split1(v.z, h[2], l[2]); split1(v.w, h[3], l[3]);
  uint2 hp = make_uint2((unsigned)h[0] | ((unsigned)h[1] << 16),
                        (unsigned)h[2] | ((unsigned)h[3] << 16));
  uint2 lp = make_uint2((unsigned)l[0] | ((unsigned)l[1] << 16),
                        (unsigned)l[2] | ((unsigned)l[3] << 16));
  __nv_bfloat16* base = dst + (size_t)m * kKS;
  *(uint2*)(base + t * 4) = hp;
  *(uint2*)(base + 1024 + t * 4) = lp;
  *(uint2*)(base + 2048 + t * 4) = hp;
}

__global__ __launch_bounds__(256) void split_w_kernel(
    const float* __restrict__ Wq, const float* __restrict__ Wk,
    const float* __restrict__ Wv) {
  const int ng = blockIdx.x;
  const int mat = ng >> 10;
  const int h = (ng >> 6) & 15;
  const int n = ng & 63;
  const float* W = (mat == 0 ? Wq : (mat == 1 ? Wk : Wv));
  const float* src = W + (size_t)h * kD * kDK + n;
  __nv_bfloat16* dst = g_ws + (size_t)ng * kKS;
#pragma unroll
  for (int it = 0; it < 4; ++it) {
    int d = threadIdx.x + it * 256;
    unsigned short hh, ll;
    split1(src[(size_t)d * kDK], hh, ll);
    dst[d] = __ushort_as_bfloat16(hh);
    dst[1024 + d] = __ushort_as_bfloat16(hh);
    dst[2048 + d] = __ushort_as_bfloat16(ll);
  }
}

__global__ __launch_bounds__(256) void split_wo_kernel(
    const float* __restrict__ Wo) {
  const int n = blockIdx.x;
  __nv_bfloat16* dst = g_wos + (size_t)n * kKS;
#pragma unroll
  for (int it = 0; it < 4; ++it) {
    int d = threadIdx.x + it * 256;
    unsigned short hh, ll;
    split1(Wo[(size_t)d * kD + n], hh, ll);
    dst[d] = __ushort_as_bfloat16(hh);
    dst[1024 + d] = __ushort_as_bfloat16(hh);
    dst[2048 + d] = __ushort_as_bfloat16(ll);
  }
}

// ---------------------------------------------------------------------------
// HMMA GEMM: C[128 x 128] = A[128 x 3072] * B[128 x 3072]^T (bf16 -> f32).
// 256 thr = 8 warps (2M x 4N), warp tile 64x32, cp.async double buffer.
// B fragments via 2x ldmatrix.x4 (pairing proven in attn_smax).
// ---------------------------------------------------------------------------
__global__ __launch_bounds__(256) void mm_bf16_kernel(
    const __nv_bfloat16* __restrict__ A, const __nv_bfloat16* __restrict__ Bm,
    float* __restrict__ outP, int mode) {
  extern __shared__ char smem[];
  const unsigned sbase = smem_u32(smem);
  const unsigned aA[2] = {sbase, sbase + 16384};
  const unsigned aB[2] = {sbase + 32768, sbase + 49152};

  const int tid = threadIdx.x;
  const int wid = tid >> 5, lane = tid & 31;
  const int m0 = blockIdx.x * 128, n0 = blockIdx.y * 128;
  const int wm = (wid >> 2) * 64, wn = (wid & 3) * 32;
  const __nv_bfloat16* Asrc = A + (size_t)m0 * kKS;
  const __nv_bfloat16* Bsrc = Bm + (size_t)n0 * kKS;

  float acc[4][4][4];
#pragma unroll
  for (int mi = 0; mi < 4; ++mi)
#pragma unroll
    for (int ni = 0; ni < 4; ++ni)
#pragma unroll
      for (int r = 0; r < 4; ++r) acc[mi][ni][r] = 0.f;

#define STAGE(sbuf, ch)                                                        \
  do {                                                                         \
    _Pragma("unroll") for (int i_ = 0; i_ < 4; ++i_) {                         \
      int idx_ = tid + i_ * 256;                                               \
      int r_ = idx_ >> 3, sg_ = idx_ & 7;                                      \
      unsigned sw_ = ((unsigned)(sg_ ^ (r_ & 7))) << 4;                        \
      cpasync16(aA[sbuf] + r_ * 128 + sw_,                                     \
                Asrc + (size_t)r_ * kKS + (ch) * 64 + sg_ * 8);                \
      cpasync16(aB[sbuf] + r_ * 128 + sw_,                                     \
                Bsrc + (size_t)r_ * kKS + (ch) * 64 + sg_ * 8);                \
    }                                                                          \
    asm volatile("cp.async.commit_group;" ::: "memory");                       \
  } while (0)

  STAGE(0, 0);
  for (int ch = 0; ch < kKS / 64; ++ch) {
    const int s = ch & 1;
    if (ch < kKS / 64 - 1) {
      STAGE(s ^ 1, ch + 1);
      asm volatile("cp.async.wait_group 1;" ::: "memory");
    } else {
      asm volatile("cp.async.wait_group 0;" ::: "memory");
    }
    __syncthreads();
#pragma unroll
    for (int ks = 0; ks < 4; ++ks) {
      unsigned af[4][4], bq[2][4];
      const int cs = ks * 2 + (lane >> 4);
#pragma unroll
      for (int mi = 0; mi < 4; ++mi) {
        int row = wm + mi * 16 + (lane & 15);
        ldmx4(af[mi], aA[s] + row * 128 + ((unsigned)(cs ^ (row & 7)) << 4));
      }
#pragma unroll
      for (int nj = 0; nj < 2; ++nj) {
        int row = wn + nj * 16 + (lane & 15);
        ldmx4(bq[nj], aB[s] + row * 128 + ((unsigned)(cs ^ (row & 7)) << 4));
      }
#pragma unroll
      for (int mi = 0; mi < 4; ++mi) {
        mma_bf16(acc[mi][0], af[mi], bq[0][0], bq[0][2]);
        mma_bf16(acc[mi][1], af[mi], bq[0][1], bq[0][3]);
        mma_bf16(acc[mi][2], af[mi], bq[1][0], bq[1][2]);
        mma_bf16(acc[mi][3], af[mi], bq[1][1], bq[1][3]);
      }
    }
    __syncthreads();
  }
#undef STAGE

  const int b = m0 >> 11;
  const int mat = n0 >> 10;
  float* qkvout = (mat == 0 ? g_q : (mat == 1 ? g_k : g_v));
#pragma unroll
  for (int mi = 0; mi < 4; ++mi) {
#pragma unroll
    for (int ni = 0; ni < 4; ++ni) {
      int rl = wm + mi * 16 + (lane >> 2);
      int n = n0 + wn + ni * 8 + (lane & 3) * 2;
      if (mode == 0) {
        int h = (n >> 6) & 15, dk = n & 63;
        size_t rowbase = (size_t)(b * kH + h) * kS + (m0 & (kS - 1));
        *(float2*)&qkvout[(rowbase + rl) * kDK + dk] =
            make_float2(acc[mi][ni][0], acc[mi][ni][1]);
        *(float2*)&qkvout[(rowbase + rl + 8) * kDK + dk] =
            make_float2(acc[mi][ni][2], acc[mi][ni][3]);
      } else {
        int m = m0 + rl;
        *(float2*)&outP[(size_t)m * kD + n] =
            make_float2(acc[mi][ni][0], acc[mi][ni][1]);
        *(float2*)&outP[(size_t)(m + 8) * kD + n] =
            make_float2(acc[mi][ni][2], acc[mi][ni][3]);
      }
    }
  }
}

// ---------------------------------------------------------------------------
// attn_smax: S ~= Qhi Khi^T via HMMA (single product), row max + shortlist.
// Also stores the approx row max (used by gather as the softmax shift).
// smem: Qhi 16K + Khi 16K + cnt 512 + slots 8K = 41472 B.
// ---------------------------------------------------------------------------
__global__ __launch_bounds__(256) void attn_smax_kernel() {
  extern __shared__ char sm[];
  const unsigned sb = smem_u32(sm);
  const unsigned aQhi = sb, aKhi = sb + 16384;
  int* scnt = (int*)(sm + 32768);
  unsigned short* stid = (unsigned short*)(sm + 33280);

  const int tid = threadIdx.x;
  const int warp = tid >> 5, lane = tid & 31;
  const int qt = blockIdx.x, h = blockIdx.y, b = blockIdx.z;
  const int bh = b * kH + h;

  if (tid < 128) scnt[tid] = 0;

  const float* qsrc = g_q + ((size_t)bh * kS + qt * 128) * kDK;
#pragma unroll
  for (int it = 0; it < 4; ++it) {
    int idx = tid + it * 256;
    int row = idx >> 3, g = idx & 7;
    float v[8];
    float4 v0 = *(const float4*)&qsrc[(size_t)row * kDK + g * 8];
    float4 v1 = *(const float4*)&qsrc[(size_t)row * kDK + g * 8 + 4];
    v[0] = v0.x * 0.125f; v[1] = v0.y * 0.125f; v[2] = v0.z * 0.125f;
    v[3] = v0.w * 0.125f; v[4] = v1.x * 0.125f; v[5] = v1.y * 0.125f;
    v[6] = v1.z * 0.125f; v[7] = v1.w * 0.125f;
    unsigned sw = ((unsigned)(g ^ (row & 7))) << 4;
    *(uint4*)(sm + row * 128 + sw) = pack8hi(v);
  }

  float m0 = -3.0e38f, m1 = -3.0e38f;
  const int r0 = (warp << 4) + (lane >> 2);

  for (int kt = 0; kt < kS / 128; ++kt) {
    const float* ksrc = g_k + ((size_t)bh * kS + kt * 128) * kDK;
#pragma unroll
    for (int it = 0; it < 4; ++it) {
      int idx = tid + it * 256;
      int row = idx >> 3, g = idx & 7;
      float v[8];
      float4 v0 = *(const float4*)&ksrc[(size_t)row * kDK + g * 8];
      float4 v1 = *(const float4*)&ksrc[(size_t)row * kDK + g * 8 + 4];
      v[0] = v0.x; v[1] = v0.y; v[2] = v0.z; v[3] = v0.w;
      v[4] = v1.x; v[5] = v1.y; v[6] = v1.z; v[7] = v1.w;
      unsigned sw = ((unsigned)(g ^ (row & 7))) << 4;
      *(uint4*)(sm + 16384 + row * 128 + sw) = pack8hi(v);
    }
    __syncthreads();

    float acc[16][4];
#pragma unroll
    for (int tt = 0; tt < 16; ++tt)
#pragma unroll
      for (int j = 0; j < 4; ++j) acc[tt][j] = 0.f;

#pragma unroll
    for (int kc = 0; kc < 4; ++kc) {
      unsigned aHi[4];
      const int cs = kc * 2 + (lane >> 4);
      int rowq = (warp << 4) + (lane & 15);
      unsigned swq = ((unsigned)(cs ^ (rowq & 7))) << 4;
      ldmx4(aHi, aQhi + rowq * 128 + swq);
#pragma unroll
      for (int t3 = 0; t3 < 8; ++t3) {
        int rowb = t3 * 16 + (lane & 15);
        unsigned swb = ((unsigned)(cs ^ (rowb & 7))) << 4;
        unsigned kb[4];
        ldmx4(kb, aKhi + rowb * 128 + swb);
        mma_bf16(acc[t3 * 2], aHi, kb[0], kb[2]);
        mma_bf16(acc[t3 * 2 + 1], aHi, kb[1], kb[3]);
      }
    }

    float lm0 = -3.0e38f, lm1 = -3.0e38f;
#pragma unroll
    for (int tt = 0; tt < 16; ++tt) {
      lm0 = fmaxf(lm0, fmaxf(acc[tt][0], acc[tt][1]));
      lm1 = fmaxf(lm1, fmaxf(acc[tt][2], acc[tt][3]));
    }
    lm0 = fmaxf(lm0, __shfl_xor_sync(0xffffffffu, lm0, 1));
    lm0 = fmaxf(lm0, __shfl_xor_sync(0xffffffffu, lm0, 2));
    lm1 = fmaxf(lm1, __shfl_xor_sync(0xffffffffu, lm1, 1));
    lm1 = fmaxf(lm1, __shfl_xor_sync(0xffffffffu, lm1, 2));
    m0 = fmaxf(m0, lm0);
    m1 = fmaxf(m1, lm1);

    float th0 = m0 - 70.f, th1 = m1 - 70.f;
#pragma unroll
    for (int tt = 0; tt < 16; ++tt) {
      int tb = kt * 128 + tt * 8 + (lane & 3) * 2;
      if (acc[tt][0] > th0) {
        int i = atomicAdd(&scnt[r0], 1);
        if (i < kCap) stid[r0 * kCap + i] = (unsigned short)tb;
      }
      if (acc[tt][1] > th0) {
        int i = atomicAdd(&scnt[r0], 1);
        if (i < kCap) stid[r0 * kCap + i] = (unsigned short)(tb + 1);
      }
      if (acc[tt][2] > th1) {
        int i = atomicAdd(&scnt[r0 + 8], 1);
        if (i < kCap) stid[(r0 + 8) * kCap + i] = (unsigned short)tb;
      }
      if (acc[tt][3] > th1) {
        int i = atomicAdd(&scnt[r0 + 8], 1);
        if (i < kCap) stid[(r0 + 8) * kCap + i] = (unsigned short)(tb + 1);
      }
    }
    __syncthreads();
  }

  // row max out (all lanes in a quad agree; quad leader writes)
  {
    size_t rowg_base = ((size_t)bh * 16 + qt) * 128;
    if ((lane & 3) == 0) {
      g_rowmax[rowg_base + r0] = m0;
      g_rowmax[rowg_base + r0 + 8] = m1;
    }
  }

  if (tid < 128) {
    size_t row_g = ((size_t)bh * 16 + qt) * 128 + tid;
    int c = scnt[tid];
    g_cnt[row_g] = c;
    int cc = c < kCap ? c : kCap;
    for (int i = 0; i < cc; ++i) g_slot[row_g * kCap + i] = stid[tid * kCap + i];
  }
}

// ---------------------------------------------------------------------------
// attn_gather: warp per q-row; exact fp32 softmax over shortlist using the
// smax-provided shift (single pass); gathers V; writes bf16 [hi|lo|hi] split.
// ---------------------------------------------------------------------------
__global__ __launch_bounds__(256) void attn_gather_kernel() {
  const int warp = threadIdx.x >> 5, lane = threadIdx.x & 31;
  const size_t row_g = (size_t)blockIdx.x * 8 + warp;
  const int qrow = (int)(row_g & 127);
  const int qt = (int)((row_g >> 7) & 15);
  const int h = (int)((row_g >> 11) & 15);
  const int b = (int)(row_g >> 15);
  const int bh = b * kH + h;
  const int sq = qt * 128 + qrow;

  const float* qp = g_q + ((size_t)bh * kS + sq) * kDK;
  const float* kb = g_k + (size_t)bh * kS * kDK;
  const float* vb = g_v + (size_t)bh * kS * kDK;

  const float q0 = qp[lane] * 0.125f, q1 = qp[lane + 32] * 0.125f;
  const int cnt = g_cnt[row_g];

  float l = 0.f, a0 = 0.f, a1 = 0.f;
  if (cnt <= kCap) {
    const float m = g_rowmax[row_g];  // approx max; shift cancels exactly
    const unsigned short* sl = g_slot + row_g * kCap;
    for (int i = 0; i < cnt; ++i) {
      int t = sl[i];
      float d = q0 * kb[(size_t)t * kDK + lane] + q1 * kb[(size_t)t * kDK + lane + 32];
#pragma unroll
      for (int o = 16; o > 0; o >>= 1) d += __shfl_xor_sync(0xffffffffu, d, o);
      float p = __expf(d - m);
      l += p;
      a0 += p * vb[(size_t)t * kDK + lane];
      a1 += p * vb[(size_t)t * kDK + lane + 32];
    }
  } else {
    float m = -3.0e38f;
    for (int t = 0; t < kS; ++t) {
      float d = q0 * kb[(size_t)t * kDK + lane] + q1 * kb[(size_t)t * kDK + lane + 32];
#pragma unroll
      for (int o = 16; o > 0; o >>= 1) d += __shfl_xor_sync(0xffffffffu, d, o);
      float v0 = vb[(size_t)t * kDK + lane], v1 = vb[(size_t)t * kDK + lane + 32];
      if (d > m) {
        float c = __expf(m - d);
        m = d;
        l = l * c + 1.f;
        a0 = a0 * c + v0;
        a1 = a1 * c + v1;
      } else {
        float p = __expf(d - m);
        l += p;
        a0 += p * v0;
        a1 += p * v1;
      }
    }
  }
  float inv = 1.f / l;
  float o0 = a0 * inv, o1 = a1 * inv;
  unsigned short h0, l0, h1, l1;
  split1(o0, h0, l0);
  split1(o1, h1, l1);
  __nv_bfloat16* base = g_aos + ((size_t)b * kS + sq) * kKS + h * kDK;
  base[lane] = __ushort_as_bfloat16(h0);
  base[lane + 32] = __ushort_as_bfloat16(h1);
  base[1024 + lane] = __ushort_as_bfloat16(l0);
  base[1024 + lane + 32] = __ushort_as_bfloat16(l1);
  base[2048 + lane] = __ushort_as_bfloat16(h0);
  base[2048 + lane + 32] = __ushort_as_bfloat16(h1);
}

// ---------------------------------------------------------------------------
extern "C" void kernel_launch(void* const* d_in, const int* in_sizes, int n_in,
                              void* d_out, int out_size) {
  (void)in_sizes; (void)n_in; (void)out_size;
  const float* x  = (const float*)d_in[0];
  const float* Wq = (const float*)d_in[1];
  const float* Wk = (const float*)d_in[2];
  const float* Wv = (const float*)d_in[3];
  const float* Wo = (const float*)d_in[4];
  float* out = (float*)d_out;

  static int attr_set = 0;
  if (!attr_set) {
    cudaFuncSetAttribute(mm_bf16_kernel,
                         cudaFuncAttributeMaxDynamicSharedMemorySize, 65536);
    cudaFuncSetAttribute(attn_smax_kernel,
                         cudaFuncAttributeMaxDynamicSharedMemorySize, 41472);
    attr_set = 1;
  }

  __nv_bfloat16* xs;  cudaGetSymbolAddress((void**)&xs, g_xs);
  __nv_bfloat16* ws;  cudaGetSymbolAddress((void**)&ws, g_ws);
  __nv_bfloat16* wos; cudaGetSymbolAddress((void**)&wos, g_wos);
  __nv_bfloat16* aos; cudaGetSymbolAddress((void**)&aos, g_aos);

  split_act_kernel<<<kB * kS, 256>>>(x, xs);
  split_w_kernel<<<3 * kH * kDK, 256>>>(Wq, Wk, Wv);
  split_wo_kernel<<<kD, 256>>>(Wo);
  mm_bf16_kernel<<<dim3(kB * kS / 128, kKS / 128), 256, 65536>>>(xs, ws, nullptr, 0);
  attn_smax_kernel<<<dim3(kS / 128, kH, kB), 256, 41472>>>();
  attn_gather_kernel<<<kB * kH * kS / 8, 256>>>();
  mm_bf16_kernel<<<dim3(kB * kS / 128, kD / 128), 256, 65536>>>(aos, wos, out, 1);
}

// round 14
// speedup vs baseline: 1.1286x; 1.0256x over previous
#include <cuda_runtime.h>
#include <cuda_bf16.h>

constexpr int kB = 4, kS = 2048, kD = 1024, kH = 16, kDK = 64;
constexpr int kKS = 3072;  // split K dimension [hi | lo | hi]
constexpr int kCap = 32;   // shortlist capacity per row

__device__ __forceinline__ unsigned smem_u32(const void* p) {
  unsigned a;
  asm("{ .reg .u64 t; cvta.to.shared.u64 t, %1; cvt.u32.u64 %0, t; }"
      : "=r"(a) : "l"(p));
  return a;
}

// ---------------- mma.sync helpers (sm_80-class PTX) ----------------
__device__ __forceinline__ void cpasync16(unsigned dst, const void* src) {
  asm volatile("cp.async.cg.shared.global [%0], [%1], 16;" :: "r"(dst), "l"(src));
}
__device__ __forceinline__ void ldmx4(unsigned* r, unsigned addr) {
  asm volatile("ldmatrix.sync.aligned.m8n8.x4.shared.b16 {%0,%1,%2,%3}, [%4];"
               : "=r"(r[0]), "=r"(r[1]), "=r"(r[2]), "=r"(r[3]) : "r"(addr));
}
__device__ __forceinline__ void mma_bf16(float* d, const unsigned* a,
                                         unsigned b0, unsigned b1) {
  asm volatile(
      "mma.sync.aligned.m16n8k16.row.col.f32.bf16.bf16.f32 "
      "{%0,%1,%2,%3}, {%4,%5,%6,%7}, {%8,%9}, {%0,%1,%2,%3};"
      : "+f"(d[0]), "+f"(d[1]), "+f"(d[2]), "+f"(d[3])
      : "r"(a[0]), "r"(a[1]), "r"(a[2]), "r"(a[3]), "r"(b0), "r"(b1));
}

// ---------------- scratch ----------------
__device__ __align__(16) float g_q [(size_t)kB * kH * kS * kDK];
__device__ __align__(16) float g_k [(size_t)kB * kH * kS * kDK];
__device__ __align__(16) float g_v [(size_t)kB * kH * kS * kDK];
__device__ __align__(16) __nv_bfloat16 g_qh[(size_t)kB * kH * kS * kDK];  // bf16(0.125*q)
__device__ __align__(16) __nv_bfloat16 g_kh[(size_t)kB * kH * kS * kDK];  // bf16(k)
__device__ __align__(16) __nv_bfloat16 g_xs [(size_t)kB * kS * kKS];
__device__ __align__(16) __nv_bfloat16 g_ws [(size_t)3 * kH * kDK * kKS];
__device__ __align__(16) __nv_bfloat16 g_wos[(size_t)kD * kKS];
__device__ __align__(16) __nv_bfloat16 g_aos[(size_t)kB * kS * kKS];
__device__ int            g_cnt [(size_t)kB * kH * kS];
__device__ float          g_rowmax[(size_t)kB * kH * kS];
__device__ unsigned short g_slot[(size_t)kB * kH * kS * kCap];

__device__ __forceinline__ void split1(float x, unsigned short& h,
                                       unsigned short& l) {
  __nv_bfloat16 hb = __float2bfloat16_rn(x);
  __nv_bfloat16 lb = __float2bfloat16_rn(x - __bfloat162float(hb));
  h = __bfloat16_as_ushort(hb);
  l = __bfloat16_as_ushort(lb);
}

// ---------------- split kernels ----------------
__global__ __launch_bounds__(256) void split_act_kernel(
    const float* __restrict__ src, __nv_bfloat16* __restrict__ dst) {
  const int m = blockIdx.x;
  const int t = threadIdx.x;
  float4 v = *(const float4*)&src[(size_t)m * kD + t * 4];
  unsigned short h[4], l[4];
  split1(v.x, h[0], l[0]); split1(v.y, h[1], l[1]);
  split1(v.z, h[2], l[2]); split1(v.w, h[3], l[3]);
  uint2 hp = make_uint2((unsigned)h[0] | ((unsigned)h[1] << 16),
                        (unsigned)h[2] | ((unsigned)h[3] << 16));
  uint2 lp = make_uint2((unsigned)l[0] | ((unsigned)l[1] << 16),
                        (unsigned)l[2] | ((unsigned)l[3] << 16));
  __nv_bfloat16* base = dst + (size_t)m * kKS;
  *(uint2*)(base + t * 4) = hp;
  *(uint2*)(base + 1024 + t * 4) = lp;
  *(uint2*)(base + 2048 + t * 4) = hp;
}

// merged QKV-weight + Wo split: grid 4096 (0..3071 -> g_ws, 3072.. -> g_wos)
__global__ __launch_bounds__(256) void split_weights_kernel(
    const float* __restrict__ Wq, const float* __restrict__ Wk,
    const float* __restrict__ Wv, const float* __restrict__ Wo) {
  const int ng = blockIdx.x;
  const float* src;
  __nv_bfloat16* dst;
  size_t stride;
  if (ng < 3072) {
    const int mat = ng >> 10;
    const int h = (ng >> 6) & 15;
    const int n = ng & 63;
    const float* W = (mat == 0 ? Wq : (mat == 1 ? Wk : Wv));
    src = W + (size_t)h * kD * kDK + n;
    stride = kDK;
    dst = g_ws + (size_t)ng * kKS;
  } else {
    const int n = ng - 3072;
    src = Wo + n;
    stride = kD;
    dst = g_wos + (size_t)n * kKS;
  }
#pragma unroll
  for (int it = 0; it < 4; ++it) {
    int d = threadIdx.x + it * 256;
    unsigned short hh, ll;
    split1(src[(size_t)d * stride], hh, ll);
    dst[d] = __ushort_as_bfloat16(hh);
    dst[1024 + d] = __ushort_as_bfloat16(hh);
    dst[2048 + d] = __ushort_as_bfloat16(ll);
  }
}

// ---------------------------------------------------------------------------
// HMMA GEMM (R12/R13 proven core). C[128 x 128] = A[128 x 3072] * B^T.
// mode 0: QKV. Also emits bf16 q-hi (x0.125) and k-hi panels for smax.
// mode 1: proj -> d_out.
// ---------------------------------------------------------------------------
__global__ __launch_bounds__(256) void mm_bf16_kernel(
    const __nv_bfloat16* __restrict__ A, const __nv_bfloat16* __restrict__ Bm,
    float* __restrict__ outP, int mode) {
  extern __shared__ char smem[];
  const unsigned sbase = smem_u32(smem);
  const unsigned aA[2] = {sbase, sbase + 16384};
  const unsigned aB[2] = {sbase + 32768, sbase + 49152};

  const int tid = threadIdx.x;
  const int wid = tid >> 5, lane = tid & 31;
  const int m0 = blockIdx.x * 128, n0 = blockIdx.y * 128;
  const int wm = (wid >> 2) * 64, wn = (wid & 3) * 32;
  const __nv_bfloat16* Asrc = A + (size_t)m0 * kKS;
  const __nv_bfloat16* Bsrc = Bm + (size_t)n0 * kKS;

  float acc[4][4][4];
#pragma unroll
  for (int mi = 0; mi < 4; ++mi)
#pragma unroll
    for (int ni = 0; ni < 4; ++ni)
#pragma unroll
      for (int r = 0; r < 4; ++r) acc[mi][ni][r] = 0.f;

#define STAGE(sbuf, ch)                                                        \
  do {                                                                         \
    _Pragma("unroll") for (int i_ = 0; i_ < 4; ++i_) {                         \
      int idx_ = tid + i_ * 256;                                               \
      int r_ = idx_ >> 3, sg_ = idx_ & 7;                                      \
      unsigned sw_ = ((unsigned)(sg_ ^ (r_ & 7))) << 4;                        \
      cpasync16(aA[sbuf] + r_ * 128 + sw_,                                     \
                Asrc + (size_t)r_ * kKS + (ch) * 64 + sg_ * 8);                \
      cpasync16(aB[sbuf] + r_ * 128 + sw_,                                     \
                Bsrc + (size_t)r_ * kKS + (ch) * 64 + sg_ * 8);                \
    }                                                                          \
    asm volatile("cp.async.commit_group;" ::: "memory");                       \
  } while (0)

  STAGE(0, 0);
  for (int ch = 0; ch < kKS / 64; ++ch) {
    const int s = ch & 1;
    if (ch < kKS / 64 - 1) {
      STAGE(s ^ 1, ch + 1);
      asm volatile("cp.async.wait_group 1;" ::: "memory");
    } else {
      asm volatile("cp.async.wait_group 0;" ::: "memory");
    }
    __syncthreads();
#pragma unroll
    for (int ks = 0; ks < 4; ++ks) {
      unsigned af[4][4], bq[2][4];
      const int cs = ks * 2 + (lane >> 4);
#pragma unroll
      for (int mi = 0; mi < 4; ++mi) {
        int row = wm + mi * 16 + (lane & 15);
        ldmx4(af[mi], aA[s] + row * 128 + ((unsigned)(cs ^ (row & 7)) << 4));
      }
#pragma unroll
      for (int nj = 0; nj < 2; ++nj) {
        int row = wn + nj * 16 + (lane & 15);
        ldmx4(bq[nj], aB[s] + row * 128 + ((unsigned)(cs ^ (row & 7)) << 4));
      }
#pragma unroll
      for (int mi = 0; mi < 4; ++mi) {
        mma_bf16(acc[mi][0], af[mi], bq[0][0], bq[0][2]);
        mma_bf16(acc[mi][1], af[mi], bq[0][1], bq[0][3]);
        mma_bf16(acc[mi][2], af[mi], bq[1][0], bq[1][2]);
        mma_bf16(acc[mi][3], af[mi], bq[1][1], bq[1][3]);
      }
    }
    __syncthreads();
  }
#undef STAGE

  const int b = m0 >> 11;
  const int mat = n0 >> 10;
  float* qkvout = (mat == 0 ? g_q : (mat == 1 ? g_k : g_v));
#pragma unroll
  for (int mi = 0; mi < 4; ++mi) {
#pragma unroll
    for (int ni = 0; ni < 4; ++ni) {
      int rl = wm + mi * 16 + (lane >> 2);
      int n = n0 + wn + ni * 8 + (lane & 3) * 2;
      if (mode == 0) {
        int h = (n >> 6) & 15, dk = n & 63;
        size_t rowbase = (size_t)(b * kH + h) * kS + (m0 & (kS - 1));
        *(float2*)&qkvout[(rowbase + rl) * kDK + dk] =
            make_float2(acc[mi][ni][0], acc[mi][ni][1]);
        *(float2*)&qkvout[(rowbase + rl + 8) * kDK + dk] =
            make_float2(acc[mi][ni][2], acc[mi][ni][3]);
        if (mat == 0) {
          // bf16 q-hi with 1/8 scale folded (exact power of 2)
          __nv_bfloat162 p0, p1;
          p0.x = __float2bfloat16_rn(acc[mi][ni][0] * 0.125f);
          p0.y = __float2bfloat16_rn(acc[mi][ni][1] * 0.125f);
          p1.x = __float2bfloat16_rn(acc[mi][ni][2] * 0.125f);
          p1.y = __float2bfloat16_rn(acc[mi][ni][3] * 0.125f);
          *(__nv_bfloat162*)&g_qh[(rowbase + rl) * kDK + dk] = p0;
          *(__nv_bfloat162*)&g_qh[(rowbase + rl + 8) * kDK + dk] = p1;
        } else if (mat == 1) {
          __nv_bfloat162 p0, p1;
          p0.x = __float2bfloat16_rn(acc[mi][ni][0]);
          p0.y = __float2bfloat16_rn(acc[mi][ni][1]);
          p1.x = __float2bfloat16_rn(acc[mi][ni][2]);
          p1.y = __float2bfloat16_rn(acc[mi][ni][3]);
          *(__nv_bfloat162*)&g_kh[(rowbase + rl) * kDK + dk] = p0;
          *(__nv_bfloat162*)&g_kh[(rowbase + rl + 8) * kDK + dk] = p1;
        }
      } else {
        int m = m0 + rl;
        *(float2*)&outP[(size_t)m * kD + n] =
            make_float2(acc[mi][ni][0], acc[mi][ni][1]);
        *(float2*)&outP[(size_t)(m + 8) * kD + n] =
            make_float2(acc[mi][ni][2], acc[mi][ni][3]);
      }
    }
  }
}

// ---------------------------------------------------------------------------
// attn_smax: S ~= Qhi Khi^T via HMMA; tiles loaded directly from pre-split
// bf16 panels (no in-kernel conversion). Row max + shortlist (margin 70).
// smem: Qhi 16K + Khi 16K + cnt 512 + slots 8K = 41472 B.
// ---------------------------------------------------------------------------
__global__ __launch_bounds__(256) void attn_smax_kernel() {
  extern __shared__ char sm[];
  const unsigned sb = smem_u32(sm);
  const unsigned aQhi = sb, aKhi = sb + 16384;
  int* scnt = (int*)(sm + 32768);
  unsigned short* stid = (unsigned short*)(sm + 33280);

  const int tid = threadIdx.x;
  const int warp = tid >> 5, lane = tid & 31;
  const int qt = blockIdx.x, h = blockIdx.y, b = blockIdx.z;
  const int bh = b * kH + h;

  if (tid < 128) scnt[tid] = 0;

  const __nv_bfloat16* qsrc = g_qh + ((size_t)bh * kS + qt * 128) * kDK;
#pragma unroll
  for (int it = 0; it < 4; ++it) {
    int idx = tid + it * 256;
    int row = idx >> 3, g = idx & 7;
    unsigned sw = ((unsigned)(g ^ (row & 7))) << 4;
    *(uint4*)(sm + row * 128 + sw) = *(const uint4*)(qsrc + (size_t)row * kDK + g * 8);
  }

  float m0 = -3.0e38f, m1 = -3.0e38f;
  const int r0 = (warp << 4) + (lane >> 2);

  for (int kt = 0; kt < kS / 128; ++kt) {
    const __nv_bfloat16* ksrc = g_kh + ((size_t)bh * kS + kt * 128) * kDK;
#pragma unroll
    for (int it = 0; it < 4; ++it) {
      int idx = tid + it * 256;
      int row = idx >> 3, g = idx & 7;
      unsigned sw = ((unsigned)(g ^ (row & 7))) << 4;
      *(uint4*)(sm + 16384 + row * 128 + sw) =
          *(const uint4*)(ksrc + (size_t)row * kDK + g * 8);
    }
    __syncthreads();

    float acc[16][4];
#pragma unroll
    for (int tt = 0; tt < 16; ++tt)
#pragma unroll
      for (int j = 0; j < 4; ++j) acc[tt][j] = 0.f;

#pragma unroll
    for (int kc = 0; kc < 4; ++kc) {
      unsigned aHi[4];
      const int cs = kc * 2 + (lane >> 4);
      int rowq = (warp << 4) + (lane & 15);
      unsigned swq = ((unsigned)(cs ^ (rowq & 7))) << 4;
      ldmx4(aHi, aQhi + rowq * 128 + swq);
#pragma unroll
      for (int t3 = 0; t3 < 8; ++t3) {
        int rowb = t3 * 16 + (lane & 15);
        unsigned swb = ((unsigned)(cs ^ (rowb & 7))) << 4;
        unsigned kb[4];
        ldmx4(kb, aKhi + rowb * 128 + swb);
        mma_bf16(acc[t3 * 2], aHi, kb[0], kb[2]);
        mma_bf16(acc[t3 * 2 + 1], aHi, kb[1], kb[3]);
      }
    }

    float lm0 = -3.0e38f, lm1 = -3.0e38f;
#pragma unroll
    for (int tt = 0; tt < 16; ++tt) {
      lm0 = fmaxf(lm0, fmaxf(acc[tt][0], acc[tt][1]));
      lm1 = fmaxf(lm1, fmaxf(acc[tt][2], acc[tt][3]));
    }
    lm0 = fmaxf(lm0, __shfl_xor_sync(0xffffffffu, lm0, 1));
    lm0 = fmaxf(lm0, __shfl_xor_sync(0xffffffffu, lm0, 2));
    lm1 = fmaxf(lm1, __shfl_xor_sync(0xffffffffu, lm1, 1));
    lm1 = fmaxf(lm1, __shfl_xor_sync(0xffffffffu, lm1, 2));
    m0 = fmaxf(m0, lm0);
    m1 = fmaxf(m1, lm1);

    float th0 = m0 - 70.f, th1 = m1 - 70.f;
#pragma unroll
    for (int tt = 0; tt < 16; ++tt) {
      int tb = kt * 128 + tt * 8 + (lane & 3) * 2;
      if (acc[tt][0] > th0) {
        int i = atomicAdd(&scnt[r0], 1);
        if (i < kCap) stid[r0 * kCap + i] = (unsigned short)tb;
      }
      if (acc[tt][1] > th0) {
        int i = atomicAdd(&scnt[r0], 1);
        if (i < kCap) stid[r0 * kCap + i] = (unsigned short)(tb + 1);
      }
      if (acc[tt][2] > th1) {
        int i = atomicAdd(&scnt[r0 + 8], 1);
        if (i < kCap) stid[(r0 + 8) * kCap + i] = (unsigned short)tb;
      }
      if (acc[tt][3] > th1) {
        int i = atomicAdd(&scnt[r0 + 8], 1);
        if (i < kCap) stid[(r0 + 8) * kCap + i] = (unsigned short)(tb + 1);
      }
    }
    __syncthreads();
  }

  {
    size_t rowg_base = ((size_t)bh * 16 + qt) * 128;
    if ((lane & 3) == 0) {
      g_rowmax[rowg_base + r0] = m0;
      g_rowmax[rowg_base + r0 + 8] = m1;
    }
  }

  if (tid < 128) {
    size_t row_g = ((size_t)bh * 16 + qt) * 128 + tid;
    int c = scnt[tid];
    g_cnt[row_g] = c;
    int cc = c < kCap ? c : kCap;
    for (int i = 0; i < cc; ++i) g_slot[row_g * kCap + i] = stid[tid * kCap + i];
  }
}

// ---------------------------------------------------------------------------
// attn_gather: warp per q-row; exact fp32 softmax over shortlist using the
// smax shift; gathers V; writes bf16 [hi|lo|hi] split of attn-out directly.
// ---------------------------------------------------------------------------
__global__ __launch_bounds__(256) void attn_gather_kernel() {
  const int warp = threadIdx.x >> 5, lane = threadIdx.x & 31;
  const size_t row_g = (size_t)blockIdx.x * 8 + warp;
  const int qrow = (int)(row_g & 127);
  const int qt = (int)((row_g >> 7) & 15);
  const int h = (int)((row_g >> 11) & 15);
  const int b = (int)(row_g >> 15);
  const int bh = b * kH + h;
  const int sq = qt * 128 + qrow;

  const float* qp = g_q + ((size_t)bh * kS + sq) * kDK;
  const float* kb = g_k + (size_t)bh * kS * kDK;
  const float* vb = g_v + (size_t)bh * kS * kDK;

  const float q0 = qp[lane] * 0.125f, q1 = qp[lane + 32] * 0.125f;
  const int cnt = g_cnt[row_g];

  float l = 0.f, a0 = 0.f, a1 = 0.f;
  if (cnt <= kCap) {
    const float m = g_rowmax[row_g];
    const unsigned short* sl = g_slot + row_g * kCap;
    for (int i = 0; i < cnt; ++i) {
      int t = sl[i];
      float d = q0 * kb[(size_t)t * kDK + lane] + q1 * kb[(size_t)t * kDK + lane + 32];
#pragma unroll
      for (int o = 16; o > 0; o >>= 1) d += __shfl_xor_sync(0xffffffffu, d, o);
      float p = __expf(d - m);
      l += p;
      a0 += p * vb[(size_t)t * kDK + lane];
      a1 += p * vb[(size_t)t * kDK + lane + 32];
    }
  } else {
    float m = -3.0e38f;
    for (int t = 0; t < kS; ++t) {
      float d = q0 * kb[(size_t)t * kDK + lane] + q1 * kb[(size_t)t * kDK + lane + 32];
#pragma unroll
      for (int o = 16; o > 0; o >>= 1) d += __shfl_xor_sync(0xffffffffu, d, o);
      float v0 = vb[(size_t)t * kDK + lane], v1 = vb[(size_t)t * kDK + lane + 32];
      if (d > m) {
        float c = __expf(m - d);
        m = d;
        l = l * c + 1.f;
        a0 = a0 * c + v0;
        a1 = a1 * c + v1;
      } else {
        float p = __expf(d - m);
        l += p;
        a0 += p * v0;
        a1 += p * v1;
      }
    }
  }
  float inv = 1.f / l;
  float o0 = a0 * inv, o1 = a1 * inv;
  unsigned short h0, l0, h1, l1;
  split1(o0, h0, l0);
  split1(o1, h1, l1);
  __nv_bfloat16* base = g_aos + ((size_t)b * kS + sq) * kKS + h * kDK;
  base[lane] = __ushort_as_bfloat16(h0);
  base[lane + 32] = __ushort_as_bfloat16(h1);
  base[1024 + lane] = __ushort_as_bfloat16(l0);
  base[1024 + lane + 32] = __ushort_as_bfloat16(l1);
  base[2048 + lane] = __ushort_as_bfloat16(h0);
  base[2048 + lane + 32] = __ushort_as_bfloat16(h1);
}

// ---------------------------------------------------------------------------
extern "C" void kernel_launch(void* const* d_in, const int* in_sizes, int n_in,
                              void* d_out, int out_size) {
  (void)in_sizes; (void)n_in; (void)out_size;
  const float* x  = (const float*)d_in[0];
  const float* Wq = (const float*)d_in[1];
  const float* Wk = (const float*)d_in[2];
  const float* Wv = (const float*)d_in[3];
  const float* Wo = (const float*)d_in[4];
  float* out = (float*)d_out;

  static int attr_set = 0;
  if (!attr_set) {
    cudaFuncSetAttribute(mm_bf16_kernel,
                         cudaFuncAttributeMaxDynamicSharedMemorySize, 65536);
    cudaFuncSetAttribute(attn_smax_kernel,
                         cudaFuncAttributeMaxDynamicSharedMemorySize, 41472);
    attr_set = 1;
  }

  __nv_bfloat16* xs;  cudaGetSymbolAddress((void**)&xs, g_xs);
  __nv_bfloat16* ws;  cudaGetSymbolAddress((void**)&ws, g_ws);
  __nv_bfloat16* wos; cudaGetSymbolAddress((void**)&wos, g_wos);
  __nv_bfloat16* aos; cudaGetSymbolAddress((void**)&aos, g_aos);

  split_act_kernel<<<kB * kS, 256>>>(x, xs);
  split_weights_kernel<<<3 * kH * kDK + kD, 256>>>(Wq, Wk, Wv, Wo);
  mm_bf16_kernel<<<dim3(kB * kS / 128, kKS / 128), 256, 65536>>>(xs, ws, nullptr, 0);
  attn_smax_kernel<<<dim3(kS / 128, kH, kB), 256, 41472>>>();
  attn_gather_kernel<<<kB * kH * kS / 8, 256>>>();
  mm_bf16_kernel<<<dim3(kB * kS / 128, kD / 128), 256, 65536>>>(aos, wos, out, 1);
}

// round 15
// speedup vs baseline: 1.1884x; 1.0530x over previous
#include <cuda_runtime.h>
#include <cuda_bf16.h>

constexpr int kB = 4, kS = 2048, kD = 1024, kH = 16, kDK = 64;
constexpr int kKS = 3072;  // split K dimension [hi | lo | hi]
constexpr int kCap = 32;   // shortlist capacity per row

__device__ __forceinline__ unsigned smem_u32(const void* p) {
  unsigned a;
  asm("{ .reg .u64 t; cvta.to.shared.u64 t, %1; cvt.u32.u64 %0, t; }"
      : "=r"(a) : "l"(p));
  return a;
}

// ---------------- mma.sync helpers (sm_80-class PTX) ----------------
__device__ __forceinline__ void cpasync16(unsigned dst, const void* src) {
  asm volatile("cp.async.cg.shared.global [%0], [%1], 16;" :: "r"(dst), "l"(src));
}
__device__ __forceinline__ void ldmx4(unsigned* r, unsigned addr) {
  asm volatile("ldmatrix.sync.aligned.m8n8.x4.shared.b16 {%0,%1,%2,%3}, [%4];"
               : "=r"(r[0]), "=r"(r[1]), "=r"(r[2]), "=r"(r[3]) : "r"(addr));
}
__device__ __forceinline__ void mma_bf16(float* d, const unsigned* a,
                                         unsigned b0, unsigned b1) {
  asm volatile(
      "mma.sync.aligned.m16n8k16.row.col.f32.bf16.bf16.f32 "
      "{%0,%1,%2,%3}, {%4,%5,%6,%7}, {%8,%9}, {%0,%1,%2,%3};"
      : "+f"(d[0]), "+f"(d[1]), "+f"(d[2]), "+f"(d[3])
      : "r"(a[0]), "r"(a[1]), "r"(a[2]), "r"(a[3]), "r"(b0), "r"(b1));
}

// ---------------- scratch ----------------
__device__ __align__(16) float g_q [(size_t)kB * kH * kS * kDK];
__device__ __align__(16) float g_k [(size_t)kB * kH * kS * kDK];
__device__ __align__(16) float g_v [(size_t)kB * kH * kS * kDK];
__device__ __align__(16) __nv_bfloat16 g_qh[(size_t)kB * kH * kS * kDK];  // bf16(0.125*q)
__device__ __align__(16) __nv_bfloat16 g_kh[(size_t)kB * kH * kS * kDK];  // bf16(k)
__device__ __align__(16) __nv_bfloat16 g_xs [(size_t)kB * kS * kKS];
__device__ __align__(16) __nv_bfloat16 g_ws [(size_t)3 * kH * kDK * kKS];
__device__ __align__(16) __nv_bfloat16 g_wos[(size_t)kD * kKS];
__device__ __align__(16) __nv_bfloat16 g_aos[(size_t)kB * kS * kKS];
__device__ int            g_cnt [(size_t)kB * kH * kS];
__device__ float          g_rowmax[(size_t)kB * kH * kS];
__device__ unsigned short g_slot[(size_t)kB * kH * kS * kCap];

__device__ __forceinline__ void split1(float x, unsigned short& h,
                                       unsigned short& l) {
  __nv_bfloat16 hb = __float2bfloat16_rn(x);
  __nv_bfloat16 lb = __float2bfloat16_rn(x - __bfloat162float(hb));
  h = __bfloat16_as_ushort(hb);
  l = __bfloat16_as_ushort(lb);
}

// ---------------- split kernels ----------------
__global__ __launch_bounds__(256) void split_act_kernel(
    const float* __restrict__ src, __nv_bfloat16* __restrict__ dst) {
  const int m = blockIdx.x;
  const int t = threadIdx.x;
  float4 v = *(const float4*)&src[(size_t)m * kD + t * 4];
  unsigned short h[4], l[4];
  split1(v.x, h[0], l[0]); split1(v.y, h[1], l[1]);
  split1(v.z, h[2], l[2]); split1(v.w, h[3], l[3]);
  uint2 hp = make_uint2((unsigned)h[0] | ((unsigned)h[1] << 16),
                        (unsigned)h[2] | ((unsigned)h[3] << 16));
  uint2 lp = make_uint2((unsigned)l[0] | ((unsigned)l[1] << 16),
                        (unsigned)l[2] | ((unsigned)l[3] << 16));
  __nv_bfloat16* base = dst + (size_t)m * kKS;
  *(uint2*)(base + t * 4) = hp;
  *(uint2*)(base + 1024 + t * 4) = lp;
  *(uint2*)(base + 2048 + t * 4) = hp;
}

// merged QKV-weight + Wo split: grid 4096 (0..3071 -> g_ws, 3072.. -> g_wos)
__global__ __launch_bounds__(256) void split_weights_kernel(
    const float* __restrict__ Wq, const float* __restrict__ Wk,
    const float* __restrict__ Wv, const float* __restrict__ Wo) {
  const int ng = blockIdx.x;
  const float* src;
  __nv_bfloat16* dst;
  size_t stride;
  if (ng < 3072) {
    const int mat = ng >> 10;
    const int h = (ng >> 6) & 15;
    const int n = ng & 63;
    const float* W = (mat == 0 ? Wq : (mat == 1 ? Wk : Wv));
    src = W + (size_t)h * kD * kDK + n;
    stride = kDK;
    dst = g_ws + (size_t)ng * kKS;
  } else {
    const int n = ng - 3072;
    src = Wo + n;
    stride = kD;
    dst = g_wos + (size_t)n * kKS;
  }
#pragma unroll
  for (int it = 0; it < 4; ++it) {
    int d = threadIdx.x + it * 256;
    unsigned short hh, ll;
    split1(src[(size_t)d * stride], hh, ll);
    dst[d] = __ushort_as_bfloat16(hh);
    dst[1024 + d] = __ushort_as_bfloat16(hh);
    dst[2048 + d] = __ushort_as_bfloat16(ll);
  }
}

// ---------------------------------------------------------------------------
// HMMA GEMM (R12/R13 proven core). C[128 x 128] = A[128 x 3072] * B^T.
// mode 0: QKV. Also emits bf16 q-hi (x0.125) and k-hi panels for smax.
// mode 1: proj -> d_out.
// ---------------------------------------------------------------------------
__global__ __launch_bounds__(256) void mm_bf16_kernel(
    const __nv_bfloat16* __restrict__ A, const __nv_bfloat16* __restrict__ Bm,
    float* __restrict__ outP, int mode) {
  extern __shared__ char smem[];
  const unsigned sbase = smem_u32(smem);
  const unsigned aA[2] = {sbase, sbase + 16384};
  const unsigned aB[2] = {sbase + 32768, sbase + 49152};

  const int tid = threadIdx.x;
  const int wid = tid >> 5, lane = tid & 31;
  const int m0 = blockIdx.x * 128, n0 = blockIdx.y * 128;
  const int wm = (wid >> 2) * 64, wn = (wid & 3) * 32;
  const __nv_bfloat16* Asrc = A + (size_t)m0 * kKS;
  const __nv_bfloat16* Bsrc = Bm + (size_t)n0 * kKS;

  float acc[4][4][4];
#pragma unroll
  for (int mi = 0; mi < 4; ++mi)
#pragma unroll
    for (int ni = 0; ni < 4; ++ni)
#pragma unroll
      for (int r = 0; r < 4; ++r) acc[mi][ni][r] = 0.f;

#define STAGE(sbuf, ch)                                                        \
  do {                                                                         \
    _Pragma("unroll") for (int i_ = 0; i_ < 4; ++i_) {                         \
      int idx_ = tid + i_ * 256;                                               \
      int r_ = idx_ >> 3, sg_ = idx_ & 7;                                      \
      unsigned sw_ = ((unsigned)(sg_ ^ (r_ & 7))) << 4;                        \
      cpasync16(aA[sbuf] + r_ * 128 + sw_,                                     \
                Asrc + (size_t)r_ * kKS + (ch) * 64 + sg_ * 8);                \
      cpasync16(aB[sbuf] + r_ * 128 + sw_,                                     \
                Bsrc + (size_t)r_ * kKS + (ch) * 64 + sg_ * 8);                \
    }                                                                          \
    asm volatile("cp.async.commit_group;" ::: "memory");                       \
  } while (0)

  STAGE(0, 0);
  for (int ch = 0; ch < kKS / 64; ++ch) {
    const int s = ch & 1;
    if (ch < kKS / 64 - 1) {
      STAGE(s ^ 1, ch + 1);
      asm volatile("cp.async.wait_group 1;" ::: "memory");
    } else {
      asm volatile("cp.async.wait_group 0;" ::: "memory");
    }
    __syncthreads();
#pragma unroll
    for (int ks = 0; ks < 4; ++ks) {
      unsigned af[4][4], bq[2][4];
      const int cs = ks * 2 + (lane >> 4);
#pragma unroll
      for (int mi = 0; mi < 4; ++mi) {
        int row = wm + mi * 16 + (lane & 15);
        ldmx4(af[mi], aA[s] + row * 128 + ((unsigned)(cs ^ (row & 7)) << 4));
      }
#pragma unroll
      for (int nj = 0; nj < 2; ++nj) {
        int row = wn + nj * 16 + (lane & 15);
        ldmx4(bq[nj], aB[s] + row * 128 + ((unsigned)(cs ^ (row & 7)) << 4));
      }
#pragma unroll
      for (int mi = 0; mi < 4; ++mi) {
        mma_bf16(acc[mi][0], af[mi], bq[0][0], bq[0][2]);
        mma_bf16(acc[mi][1], af[mi], bq[0][1], bq[0][3]);
        mma_bf16(acc[mi][2], af[mi], bq[1][0], bq[1][2]);
        mma_bf16(acc[mi][3], af[mi], bq[1][1], bq[1][3]);
      }
    }
    __syncthreads();
  }
#undef STAGE

  const int b = m0 >> 11;
  const int mat = n0 >> 10;
  float* qkvout = (mat == 0 ? g_q : (mat == 1 ? g_k : g_v));
#pragma unroll
  for (int mi = 0; mi < 4; ++mi) {
#pragma unroll
    for (int ni = 0; ni < 4; ++ni) {
      int rl = wm + mi * 16 + (lane >> 2);
      int n = n0 + wn + ni * 8 + (lane & 3) * 2;
      if (mode == 0) {
        int h = (n >> 6) & 15, dk = n & 63;
        size_t rowbase = (size_t)(b * kH + h) * kS + (m0 & (kS - 1));
        *(float2*)&qkvout[(rowbase + rl) * kDK + dk] =
            make_float2(acc[mi][ni][0], acc[mi][ni][1]);
        *(float2*)&qkvout[(rowbase + rl + 8) * kDK + dk] =
            make_float2(acc[mi][ni][2], acc[mi][ni][3]);
        if (mat == 0) {
          __nv_bfloat162 p0, p1;
          p0.x = __float2bfloat16_rn(acc[mi][ni][0] * 0.125f);
          p0.y = __float2bfloat16_rn(acc[mi][ni][1] * 0.125f);
          p1.x = __float2bfloat16_rn(acc[mi][ni][2] * 0.125f);
          p1.y = __float2bfloat16_rn(acc[mi][ni][3] * 0.125f);
          *(__nv_bfloat162*)&g_qh[(rowbase + rl) * kDK + dk] = p0;
          *(__nv_bfloat162*)&g_qh[(rowbase + rl + 8) * kDK + dk] = p1;
        } else if (mat == 1) {
          __nv_bfloat162 p0, p1;
          p0.x = __float2bfloat16_rn(acc[mi][ni][0]);
          p0.y = __float2bfloat16_rn(acc[mi][ni][1]);
          p1.x = __float2bfloat16_rn(acc[mi][ni][2]);
          p1.y = __float2bfloat16_rn(acc[mi][ni][3]);
          *(__nv_bfloat162*)&g_kh[(rowbase + rl) * kDK + dk] = p0;
          *(__nv_bfloat162*)&g_kh[(rowbase + rl + 8) * kDK + dk] = p1;
        }
      } else {
        int m = m0 + rl;
        *(float2*)&outP[(size_t)m * kD + n] =
            make_float2(acc[mi][ni][0], acc[mi][ni][1]);
        *(float2*)&outP[(size_t)(m + 8) * kD + n] =
            make_float2(acc[mi][ni][2], acc[mi][ni][3]);
      }
    }
  }
}

// ---------------------------------------------------------------------------
// attn_smax: S ~= Qhi Khi^T via HMMA; pre-split bf16 tiles; K tiles double-
// buffered via cp.async; hierarchical shortlist guard. Margin 70.
// smem: Qhi 16K + K0 16K + K1 16K + cnt 512 + slots 8K = 57856 B.
// ---------------------------------------------------------------------------
__global__ __launch_bounds__(256) void attn_smax_kernel() {
  extern __shared__ char sm[];
  const unsigned sb = smem_u32(sm);
  const unsigned aQhi = sb;
  const unsigned aK[2] = {sb + 16384, sb + 32768};
  int* scnt = (int*)(sm + 49152);
  unsigned short* stid = (unsigned short*)(sm + 49664);

  const int tid = threadIdx.x;
  const int warp = tid >> 5, lane = tid & 31;
  const int qt = blockIdx.x, h = blockIdx.y, b = blockIdx.z;
  const int bh = b * kH + h;

  if (tid < 128) scnt[tid] = 0;

  const __nv_bfloat16* qsrc = g_qh + ((size_t)bh * kS + qt * 128) * kDK;
#pragma unroll
  for (int it = 0; it < 4; ++it) {
    int idx = tid + it * 256;
    int row = idx >> 3, g = idx & 7;
    unsigned sw = ((unsigned)(g ^ (row & 7))) << 4;
    *(uint4*)(sm + row * 128 + sw) = *(const uint4*)(qsrc + (size_t)row * kDK + g * 8);
  }

  const __nv_bfloat16* ksrc = g_kh + (size_t)bh * kS * kDK;

#define KSTAGE(sbuf, kt)                                                       \
  do {                                                                         \
    _Pragma("unroll") for (int i_ = 0; i_ < 4; ++i_) {                         \
      int idx_ = tid + i_ * 256;                                               \
      int r_ = idx_ >> 3, g_ = idx_ & 7;                                       \
      unsigned sw_ = ((unsigned)(g_ ^ (r_ & 7))) << 4;                         \
      cpasync16(aK[sbuf] + r_ * 128 + sw_,                                     \
                ksrc + ((size_t)(kt) * 128 + r_) * kDK + g_ * 8);              \
    }                                                                          \
    asm volatile("cp.async.commit_group;" ::: "memory");                       \
  } while (0)

  float m0 = -3.0e38f, m1 = -3.0e38f;
  const int r0 = (warp << 4) + (lane >> 2);
  constexpr int NT = kS / 128;  // 16

  KSTAGE(0, 0);
  for (int kt = 0; kt < NT; ++kt) {
    const int s = kt & 1;
    if (kt < NT - 1) {
      KSTAGE(s ^ 1, kt + 1);
      asm volatile("cp.async.wait_group 1;" ::: "memory");
    } else {
      asm volatile("cp.async.wait_group 0;" ::: "memory");
    }
    __syncthreads();

    float acc[16][4];
#pragma unroll
    for (int tt = 0; tt < 16; ++tt)
#pragma unroll
      for (int j = 0; j < 4; ++j) acc[tt][j] = 0.f;

#pragma unroll
    for (int kc = 0; kc < 4; ++kc) {
      unsigned aHi[4];
      const int cs = kc * 2 + (lane >> 4);
      int rowq = (warp << 4) + (lane & 15);
      unsigned swq = ((unsigned)(cs ^ (rowq & 7))) << 4;
      ldmx4(aHi, aQhi + rowq * 128 + swq);
#pragma unroll
      for (int t3 = 0; t3 < 8; ++t3) {
        int rowb = t3 * 16 + (lane & 15);
        unsigned swb = ((unsigned)(cs ^ (rowb & 7))) << 4;
        unsigned kb[4];
        ldmx4(kb, aK[s] + rowb * 128 + swb);
        mma_bf16(acc[t3 * 2], aHi, kb[0], kb[2]);
        mma_bf16(acc[t3 * 2 + 1], aHi, kb[1], kb[3]);
      }
    }

    float lm0 = -3.0e38f, lm1 = -3.0e38f;
#pragma unroll
    for (int tt = 0; tt < 16; ++tt) {
      lm0 = fmaxf(lm0, fmaxf(acc[tt][0], acc[tt][1]));
      lm1 = fmaxf(lm1, fmaxf(acc[tt][2], acc[tt][3]));
    }
    lm0 = fmaxf(lm0, __shfl_xor_sync(0xffffffffu, lm0, 1));
    lm0 = fmaxf(lm0, __shfl_xor_sync(0xffffffffu, lm0, 2));
    lm1 = fmaxf(lm1, __shfl_xor_sync(0xffffffffu, lm1, 1));
    lm1 = fmaxf(lm1, __shfl_xor_sync(0xffffffffu, lm1, 2));
    m0 = fmaxf(m0, lm0);
    m1 = fmaxf(m1, lm1);

    // hierarchical shortlist guard: pair max gates the element checks (exact)
    float th0 = m0 - 70.f, th1 = m1 - 70.f;
#pragma unroll
    for (int tt = 0; tt < 16; ++tt) {
      int tb = kt * 128 + tt * 8 + (lane & 3) * 2;
      if (fmaxf(acc[tt][0], acc[tt][1]) > th0) {
        if (acc[tt][0] > th0) {
          int i = atomicAdd(&scnt[r0], 1);
          if (i < kCap) stid[r0 * kCap + i] = (unsigned short)tb;
        }
        if (acc[tt][1] > th0) {
          int i = atomicAdd(&scnt[r0], 1);
          if (i < kCap) stid[r0 * kCap + i] = (unsigned short)(tb + 1);
        }
      }
      if (fmaxf(acc[tt][2], acc[tt][3]) > th1) {
        if (acc[tt][2] > th1) {
          int i = atomicAdd(&scnt[r0 + 8], 1);
          if (i < kCap) stid[(r0 + 8) * kCap + i] = (unsigned short)tb;
        }
        if (acc[tt][3] > th1) {
          int i = atomicAdd(&scnt[r0 + 8], 1);
          if (i < kCap) stid[(r0 + 8) * kCap + i] = (unsigned short)(tb + 1);
        }
      }
    }
    __syncthreads();
  }
#undef KSTAGE

  {
    size_t rowg_base = ((size_t)bh * 16 + qt) * 128;
    if ((lane & 3) == 0) {
      g_rowmax[rowg_base + r0] = m0;
      g_rowmax[rowg_base + r0 + 8] = m1;
    }
  }

  if (tid < 128) {
    size_t row_g = ((size_t)bh * 16 + qt) * 128 + tid;
    int c = scnt[tid];
    g_cnt[row_g] = c;
    int cc = c < kCap ? c : kCap;
    for (int i = 0; i < cc; ++i) g_slot[row_g * kCap + i] = stid[tid * kCap + i];
  }
}

// ---------------------------------------------------------------------------
// attn_gather: warp per q-row; exact fp32 softmax over shortlist using the
// smax shift; gathers V; writes bf16 [hi|lo|hi] split of attn-out directly.
// ---------------------------------------------------------------------------
__global__ __launch_bounds__(256) void attn_gather_kernel() {
  const int warp = threadIdx.x >> 5, lane = threadIdx.x & 31;
  const size_t row_g = (size_t)blockIdx.x * 8 + warp;
  const int qrow = (int)(row_g & 127);
  const int qt = (int)((row_g >> 7) & 15);
  const int h = (int)((row_g >> 11) & 15);
  const int b = (int)(row_g >> 15);
  const int bh = b * kH + h;
  const int sq = qt * 128 + qrow;

  const float* qp = g_q + ((size_t)bh * kS + sq) * kDK;
  const float* kb = g_k + (size_t)bh * kS * kDK;
  const float* vb = g_v + (size_t)bh * kS * kDK;

  const float q0 = qp[lane] * 0.125f, q1 = qp[lane + 32] * 0.125f;
  const int cnt = g_cnt[row_g];

  float l = 0.f, a0 = 0.f, a1 = 0.f;
  if (cnt <= kCap) {
    const float m = g_rowmax[row_g];
    const unsigned short* sl = g_slot + row_g * kCap;
    for (int i = 0; i < cnt; ++i) {
      int t = sl[i];
      float d = q0 * kb[(size_t)t * kDK + lane] + q1 * kb[(size_t)t * kDK + lane + 32];
#pragma unroll
      for (int o = 16; o > 0; o >>= 1) d += __shfl_xor_sync(0xffffffffu, d, o);
      float p = __expf(d - m);
      l += p;
      a0 += p * vb[(size_t)t * kDK + lane];
      a1 += p * vb[(size_t)t * kDK + lane + 32];
    }
  } else {
    float m = -3.0e38f;
    for (int t = 0; t < kS; ++t) {
      float d = q0 * kb[(size_t)t * kDK + lane] + q1 * kb[(size_t)t * kDK + lane + 32];
#pragma unroll
      for (int o = 16; o > 0; o >>= 1) d += __shfl_xor_sync(0xffffffffu, d, o);
      float v0 = vb[(size_t)t * kDK + lane], v1 = vb[(size_t)t * kDK + lane + 32];
      if (d > m) {
        float c = __expf(m - d);
        m = d;
        l = l * c + 1.f;
        a0 = a0 * c + v0;
        a1 = a1 * c + v1;
      } else {
        float p = __expf(d - m);
        l += p;
        a0 += p * v0;
        a1 += p * v1;
      }
    }
  }
  float inv = 1.f / l;
  float o0 = a0 * inv, o1 = a1 * inv;
  unsigned short h0, l0, h1, l1;
  split1(o0, h0, l0);
  split1(o1, h1, l1);
  __nv_bfloat16* base = g_aos + ((size_t)b * kS + sq) * kKS + h * kDK;
  base[lane] = __ushort_as_bfloat16(h0);
  base[lane + 32] = __ushort_as_bfloat16(h1);
  base[1024 + lane] = __ushort_as_bfloat16(l0);
  base[1024 + lane + 32] = __ushort_as_bfloat16(l1);
  base[2048 + lane] = __ushort_as_bfloat16(h0);
  base[2048 + lane + 32] = __ushort_as_bfloat16(h1);
}

// ---------------------------------------------------------------------------
extern "C" void kernel_launch(void* const* d_in, const int* in_sizes, int n_in,
                              void* d_out, int out_size) {
  (void)in_sizes; (void)n_in; (void)out_size;
  const float* x  = (const float*)d_in[0];
  const float* Wq = (const float*)d_in[1];
  const float* Wk = (const float*)d_in[2];
  const float* Wv = (const float*)d_in[3];
  const float* Wo = (const float*)d_in[4];
  float* out = (float*)d_out;

  static int attr_set = 0;
  if (!attr_set) {
    cudaFuncSetAttribute(mm_bf16_kernel,
                         cudaFuncAttributeMaxDynamicSharedMemorySize, 65536);
    cudaFuncSetAttribute(attn_smax_kernel,
                         cudaFuncAttributeMaxDynamicSharedMemorySize, 57856);
    attr_set = 1;
  }

  __nv_bfloat16* xs;  cudaGetSymbolAddress((void**)&xs, g_xs);
  __nv_bfloat16* ws;  cudaGetSymbolAddress((void**)&ws, g_ws);
  __nv_bfloat16* wos; cudaGetSymbolAddress((void**)&wos, g_wos);
  __nv_bfloat16* aos; cudaGetSymbolAddress((void**)&aos, g_aos);

  split_act_kernel<<<kB * kS, 256>>>(x, xs);
  split_weights_kernel<<<3 * kH * kDK + kD, 256>>>(Wq, Wk, Wv, Wo);
  mm_bf16_kernel<<<dim3(kB * kS / 128, kKS / 128), 256, 65536>>>(xs, ws, nullptr, 0);
  attn_smax_kernel<<<dim3(kS / 128, kH, kB), 256, 57856>>>();
  attn_gather_kernel<<<kB * kH * kS / 8, 256>>>();
  mm_bf16_kernel<<<dim3(kB * kS / 128, kD / 128), 256, 65536>>>(aos, wos, out, 1);
}